// round 14
// baseline (speedup 1.0000x reference)
#include <cuda_runtime.h>
#include <cuda_bf16.h>
#include <cstdint>

// Problem constants
#define TOK   16384
#define CDIM  256
#define NHEAD 8
#define DHEAD 32
#define SCALE 0.17677669529663687f  // 1/sqrt(32)

// Scratch (static device globals — allocation-free per harness rules)
__device__ float g_x0[TOK * CDIM];
__device__ float g_x1[TOK * CDIM];
__device__ float g_x2[TOK * CDIM];
__device__ float g_p [TOK * CDIM];
__device__ float g_qb[TOK * CDIM];
__device__ float g_kb[TOK * CDIM];
__device__ float g_vb[TOK * CDIM];
__device__ float g_ob[TOK * CDIM];
__device__ float g_mb[TOK * CDIM];

// ---------------------------------------------------------------------------
// Common MMA helpers
// ---------------------------------------------------------------------------
#define LDSR 40   // padded smem row stride in bf16 (80B: ldmatrix conflict-free)

__device__ __forceinline__ void mma_bf16(float* d, const uint32_t* a, const uint32_t* b) {
    asm volatile(
        "mma.sync.aligned.m16n8k16.row.col.f32.bf16.bf16.f32 "
        "{%0,%1,%2,%3}, {%4,%5,%6,%7}, {%8,%9}, {%0,%1,%2,%3};"
        : "+f"(d[0]), "+f"(d[1]), "+f"(d[2]), "+f"(d[3])
        : "r"(a[0]), "r"(a[1]), "r"(a[2]), "r"(a[3]), "r"(b[0]), "r"(b[1]));
}

__device__ __forceinline__ void ldsm_x4(uint32_t* r, const __nv_bfloat16* p) {
    uint32_t addr = (uint32_t)__cvta_generic_to_shared(p);
    asm volatile("ldmatrix.sync.aligned.m8n8.x4.shared.b16 {%0,%1,%2,%3}, [%4];"
                 : "=r"(r[0]), "=r"(r[1]), "=r"(r[2]), "=r"(r[3]) : "r"(addr));
}

__device__ __forceinline__ void ldsm_x2(uint32_t* r, const __nv_bfloat16* p) {
    uint32_t addr = (uint32_t)__cvta_generic_to_shared(p);
    asm volatile("ldmatrix.sync.aligned.m8n8.x2.shared.b16 {%0,%1}, [%2];"
                 : "=r"(r[0]), "=r"(r[1]) : "r"(addr));
}

__device__ __forceinline__ void ldsm_x2_trans(uint32_t* r, const __nv_bfloat16* p) {
    uint32_t addr = (uint32_t)__cvta_generic_to_shared(p);
    asm volatile("ldmatrix.sync.aligned.m8n8.x2.trans.shared.b16 {%0,%1}, [%2];"
                 : "=r"(r[0]), "=r"(r[1]) : "r"(addr));
}

// Truncation split: hi = top-16 bits of fp32 (packed via PRMT), lo = rn(x - hi).
__device__ __forceinline__ void pack_split(float x, float y, uint32_t* hi, uint32_t* lo) {
    uint32_t ux = __float_as_uint(x), uy = __float_as_uint(y);
    *hi = __byte_perm(ux, uy, 0x7632);
    float lx = x - __uint_as_float(ux & 0xFFFF0000u);
    float ly = y - __uint_as_float(uy & 0xFFFF0000u);
    __nv_bfloat162 lp = __floats2bfloat162_rn(lx, ly);
    *lo = *(uint32_t*)&lp;
}

// float4 (4 consecutive k) -> 2 packed hi words + 2 packed lo words, STS.64.
__device__ __forceinline__ void split_store4(__nv_bfloat16* hp, __nv_bfloat16* lp, float4 v) {
    uint32_t h01, h23, l01, l23;
    pack_split(v.x, v.y, &h01, &l01);
    pack_split(v.z, v.w, &h23, &l23);
    uint2 hw; hw.x = h01; hw.y = h23;
    uint2 lw; lw.x = l01; lw.y = l23;
    *(uint2*)hp = hw;
    *(uint2*)lp = lw;
}

// ---------------------------------------------------------------------------
// Gather: [n,c,t,h,w] -> long token layout [token= l*512+b, c]
// ---------------------------------------------------------------------------
__global__ void gather_long(const float* __restrict__ q, const float* __restrict__ k,
                            const float* __restrict__ v, const float* __restrict__ p) {
    int ct = blockIdx.x >> 1, xt = blockIdx.x & 1;
    int y  = blockIdx.y;
    int nn = blockIdx.z >> 1, t = blockIdx.z & 1;
    int c0 = ct * 32, x0 = xt * 32;
    __shared__ float sq[32][33], sk[32][33], sv[32][33], sp[32][33];
    int tx = threadIdx.x, ty = threadIdx.y;
    #pragma unroll
    for (int i = 0; i < 4; i++) {
        int ci = ty + i * 8;
        size_t idx = ((size_t)(nn * CDIM + c0 + ci) * 2 + t) * 4096 + (size_t)y * 64 + x0 + tx;
        float pv = p[idx];
        sq[ci][tx] = q[idx] + pv;
        sk[ci][tx] = k[idx] + pv;
        sv[ci][tx] = v[idx];
        sp[ci][tx] = pv;
    }
    __syncthreads();
    int bh = y >> 4, ih = y & 15;
    #pragma unroll
    for (int i = 0; i < 4; i++) {
        int xi = ty + i * 8;
        int x = x0 + xi;
        int bw = x >> 4, iw = x & 15;
        int token = (t * 16 + bh * 4 + bw) * 512 + nn * 256 + ih * 16 + iw;
        size_t o = (size_t)token * CDIM + c0 + tx;
        g_x0[o] = sq[tx][xi];
        g_x1[o] = sk[tx][xi];
        g_x2[o] = sv[tx][xi];
        g_p [o] = sp[tx][xi];
    }
}

// ---------------------------------------------------------------------------
// Tensor-core GEMM: BM=128 BN=128 BK=32, 512 threads = 16 warps (4m x 4n),
// per-warp tile 32x32 — warp-level code identical to the proven R10 kernel.
// Truncation-split bf16, double-buffered dynamic smem (80KB), STS.64 staging
// with the proven (r*LDSR + lcol4*4) map, B frags via ldsm_x4, z-fused.
// grid (2, 128, nz)  block (512)
// ---------------------------------------------------------------------------
#define GSM_AH 0
#define GSM_AL 10240
#define GSM_BH 20480
#define GSM_BL 30720
#define GSM_ELEMS 40960            // bf16 elements -> 81920 bytes

__global__ __launch_bounds__(512) void gemm_nt_tc(const float* __restrict__ X0,
                                                  const float* __restrict__ X1,
                                                  const float* __restrict__ X2,
                                                  const float* __restrict__ W0,
                                                  const float* __restrict__ bias0,
                                                  float* __restrict__ Y0,
                                                  float* __restrict__ Y1,
                                                  float* __restrict__ Y2) {
    extern __shared__ __nv_bfloat16 dsm[];
    __nv_bfloat16* As_hi = dsm + GSM_AH;   // [2][128*LDSR]
    __nv_bfloat16* As_lo = dsm + GSM_AL;
    __nv_bfloat16* Bs_hi = dsm + GSM_BH;   // [2][128*LDSR]
    __nv_bfloat16* Bs_lo = dsm + GSM_BL;

    int bz = blockIdx.z;
    const float* X = (bz == 0) ? X0 : ((bz == 1) ? X1 : X2);
    float*       Y = (bz == 0) ? Y0 : ((bz == 1) ? Y1 : Y2);
    const float* Wm   = W0 + (size_t)bz * 65536;
    const float* bias = bias0 + bz * 256;

    int tid  = threadIdx.x;
    int warp = tid >> 5, lane = tid & 31;
    int m0 = blockIdx.y * 128, n0 = blockIdx.x * 128;
    int wm = (warp >> 2) * 32;     // 4 warps over m
    int wn = (warp & 3) * 32;      // 4 warps over n

    float acc[2][4][4];
    #pragma unroll
    for (int mi = 0; mi < 2; mi++)
        #pragma unroll
        for (int ni = 0; ni < 4; ni++)
            #pragma unroll
            for (int e = 0; e < 4; e++) acc[mi][ni][e] = 0.f;

    const float4* X4 = (const float4*)X;
    const float4* W4 = (const float4*)Wm;
    int lrow  = tid >> 3;   // 0..63
    int lcol4 = tid & 7;

    int al16 = lane & 15;
    int offA = (wm + al16) * LDSR + (lane >> 4) * 8;
    int offB = (wn + al16) * LDSR + (lane >> 4) * 8;

    float4 xa[2], wb[2];
    #pragma unroll
    for (int i = 0; i < 2; i++) {
        xa[i] = X4[(size_t)(m0 + lrow + i * 64) * 64 + lcol4];
        wb[i] = W4[(size_t)(n0 + lrow + i * 64) * 64 + lcol4];
    }

    for (int kt = 0; kt < 8; kt++) {
        int buf = kt & 1;
        int sb = buf * 128 * LDSR;
        #pragma unroll
        for (int i = 0; i < 2; i++) {
            int r = lrow + i * 64;
            split_store4(&As_hi[sb + r * LDSR + lcol4 * 4],
                         &As_lo[sb + r * LDSR + lcol4 * 4], xa[i]);
            split_store4(&Bs_hi[sb + r * LDSR + lcol4 * 4],
                         &Bs_lo[sb + r * LDSR + lcol4 * 4], wb[i]);
        }
        __syncthreads();

        if (kt < 7) {
            #pragma unroll
            for (int i = 0; i < 2; i++) {
                xa[i] = X4[(size_t)(m0 + lrow + i * 64) * 64 + (kt + 1) * 8 + lcol4];
                wb[i] = W4[(size_t)(n0 + lrow + i * 64) * 64 + (kt + 1) * 8 + lcol4];
            }
        }

        const __nv_bfloat16* pa_hi0 = &As_hi[sb + offA];
        const __nv_bfloat16* pa_lo0 = &As_lo[sb + offA];
        const __nv_bfloat16* pb_hi0 = &Bs_hi[sb + offB];
        const __nv_bfloat16* pb_lo0 = &Bs_lo[sb + offB];

        #pragma unroll
        for (int kk = 0; kk < 2; kk++) {
            int ko = kk * 16;
            uint32_t ah[2][4], al[2][4];
            #pragma unroll
            for (int mi = 0; mi < 2; mi++) {
                ldsm_x4(ah[mi], pa_hi0 + mi * 16 * LDSR + ko);
                ldsm_x4(al[mi], pa_lo0 + mi * 16 * LDSR + ko);
            }
            uint32_t bh[4][2], bl[4][2];
            #pragma unroll
            for (int ni2 = 0; ni2 < 2; ni2++) {
                uint32_t r4[4];
                ldsm_x4(r4, pb_hi0 + ni2 * 16 * LDSR + ko);
                bh[2 * ni2][0] = r4[0]; bh[2 * ni2][1] = r4[2];
                bh[2 * ni2 + 1][0] = r4[1]; bh[2 * ni2 + 1][1] = r4[3];
                ldsm_x4(r4, pb_lo0 + ni2 * 16 * LDSR + ko);
                bl[2 * ni2][0] = r4[0]; bl[2 * ni2][1] = r4[2];
                bl[2 * ni2 + 1][0] = r4[1]; bl[2 * ni2 + 1][1] = r4[3];
            }
            #pragma unroll
            for (int mi = 0; mi < 2; mi++)
                #pragma unroll
                for (int ni = 0; ni < 4; ni++) {
                    mma_bf16(acc[mi][ni], ah[mi], bh[ni]);
                    mma_bf16(acc[mi][ni], ah[mi], bl[ni]);
                    mma_bf16(acc[mi][ni], al[mi], bh[ni]);
                }
        }
    }

    int cr = lane >> 2;
    int cc = (lane & 3) * 2;
    #pragma unroll
    for (int mi = 0; mi < 2; mi++) {
        #pragma unroll
        for (int ni = 0; ni < 4; ni++) {
            int col = n0 + wn + ni * 8 + cc;
            float b0 = bias[col], b1 = bias[col + 1];
            int row0 = m0 + wm + mi * 16 + cr;
            float2 o0 = make_float2(acc[mi][ni][0] + b0, acc[mi][ni][1] + b1);
            float2 o1 = make_float2(acc[mi][ni][2] + b0, acc[mi][ni][3] + b1);
            *(float2*)&Y[(size_t)row0 * CDIM + col]       = o0;
            *(float2*)&Y[(size_t)(row0 + 8) * CDIM + col] = o1;
        }
    }
}

// ---------------------------------------------------------------------------
// Attention #1 (long): Lq=Lk=32, d=32; one warp per (b,h); thread = query row.
// grid (512, 8) block (32)
// ---------------------------------------------------------------------------
__global__ void attn1(const float* __restrict__ Q, const float* __restrict__ K,
                      const float* __restrict__ V, float* __restrict__ O) {
    int b = blockIdx.x, h = blockIdx.y;
    size_t base = (size_t)b * CDIM + h * DHEAD;
    __shared__ float Ks[32][36], Vs[32][36];
    int tid = threadIdx.x;
    for (int r = 0; r < 32; r++) {
        size_t idx = (size_t)r * 131072 + base + tid;
        Ks[r][tid] = K[idx];
        Vs[r][tid] = V[idx];
    }
    __syncthreads();
    float q[32];
    const float4* q4 = (const float4*)(Q + (size_t)tid * 131072 + base);
    #pragma unroll
    for (int d4 = 0; d4 < 8; d4++) {
        float4 qq = q4[d4];
        q[d4 * 4 + 0] = qq.x * SCALE; q[d4 * 4 + 1] = qq.y * SCALE;
        q[d4 * 4 + 2] = qq.z * SCALE; q[d4 * 4 + 3] = qq.w * SCALE;
    }
    float s[32];
    float m = -1e30f;
    #pragma unroll
    for (int j = 0; j < 32; j++) {
        const float4* kr = (const float4*)Ks[j];
        float a = 0.f;
        #pragma unroll
        for (int d4 = 0; d4 < 8; d4++) {
            float4 kv = kr[d4];
            a += q[d4 * 4 + 0] * kv.x + q[d4 * 4 + 1] * kv.y
               + q[d4 * 4 + 2] * kv.z + q[d4 * 4 + 3] * kv.w;
        }
        s[j] = a;
        m = fmaxf(m, a);
    }
    float lsum = 0.f;
    #pragma unroll
    for (int j = 0; j < 32; j++) { s[j] = __expf(s[j] - m); lsum += s[j]; }
    float acc[32];
    #pragma unroll
    for (int d = 0; d < 32; d++) acc[d] = 0.f;
    #pragma unroll
    for (int j = 0; j < 32; j++) {
        const float4* vr = (const float4*)Vs[j];
        float pj = s[j];
        #pragma unroll
        for (int d4 = 0; d4 < 8; d4++) {
            float4 vv = vr[d4];
            acc[d4 * 4 + 0] += pj * vv.x; acc[d4 * 4 + 1] += pj * vv.y;
            acc[d4 * 4 + 2] += pj * vv.z; acc[d4 * 4 + 3] += pj * vv.w;
        }
    }
    float inv = 1.f / lsum;
    float4* o4 = (float4*)(O + (size_t)tid * 131072 + base);
    #pragma unroll
    for (int d4 = 0; d4 < 8; d4++) {
        float4 oo;
        oo.x = acc[d4 * 4 + 0] * inv; oo.y = acc[d4 * 4 + 1] * inv;
        oo.z = acc[d4 * 4 + 2] * inv; oo.w = acc[d4 * 4 + 3] * inv;
        o4[d4] = oo;
    }
}

// ---------------------------------------------------------------------------
// Re-index long -> short, add pos (float4 vectorized)
// grid (16384) block (64)
// ---------------------------------------------------------------------------
__global__ void reindex_short() {
    int token2 = blockIdx.x;
    int s = token2 >> 5, b2 = token2 & 31;
    int t = s >> 8, rem = s & 255, ih = rem >> 4, iw = rem & 15;
    int nn = b2 >> 4, rr = b2 & 15, bh = rr >> 2, bw = rr & 3;
    int token = (t * 16 + bh * 4 + bw) * 512 + nn * 256 + ih * 16 + iw;
    int c4 = threadIdx.x;
    size_t si = (size_t)token * 64 + c4;
    size_t di = (size_t)token2 * 64 + c4;
    float4 x  = ((const float4*)g_mb)[si];
    float4 pp = ((const float4*)g_p)[si];
    float4 xp = make_float4(x.x + pp.x, x.y + pp.y, x.z + pp.z, x.w + pp.w);
    ((float4*)g_x0)[di] = xp;
    ((float4*)g_x2)[di] = x;
}

// ---------------------------------------------------------------------------
// Attention #2 (short): FA2 on mma.sync, truncation-split bf16, double-
// buffered K/V with one barrier per tile (R12 proven).
// grid (4, 8, 32) block (256)
// ---------------------------------------------------------------------------
__global__ __launch_bounds__(256) void attn2_tc(const float* __restrict__ Q,
                                                const float* __restrict__ K,
                                                const float* __restrict__ V,
                                                float* __restrict__ O) {
    int qt = blockIdx.x, h = blockIdx.y, b2 = blockIdx.z;
    size_t base = (size_t)b2 * CDIM + h * DHEAD;
    __shared__ __nv_bfloat16 Kh[2][64 * LDSR], Kl[2][64 * LDSR];
    __shared__ __nv_bfloat16 Vh[2][64 * LDSR], Vl[2][64 * LDSR];

    int tid = threadIdx.x, warp = tid >> 5, lane = tid & 31;
    int al16 = lane & 15;
    int r  = lane >> 2;
    int cq = (lane & 3) * 2;
    int l0 = qt * 128 + warp * 16;

    uint32_t qh[2][4], ql[2][4];
    #pragma unroll
    for (int kf = 0; kf < 2; kf++) {
        #pragma unroll
        for (int half = 0; half < 2; half++) {
            int col = kf * 16 + half * 8 + cq;
            float2 v0 = *(const float2*)&Q[(size_t)(l0 + r) * 8192 + base + col];
            float2 v1 = *(const float2*)&Q[(size_t)(l0 + r + 8) * 8192 + base + col];
            v0.x *= SCALE; v0.y *= SCALE; v1.x *= SCALE; v1.y *= SCALE;
            pack_split(v0.x, v0.y, &qh[kf][half * 2 + 0], &ql[kf][half * 2 + 0]);
            pack_split(v1.x, v1.y, &qh[kf][half * 2 + 1], &ql[kf][half * 2 + 1]);
        }
    }

    float o[4][4];
    #pragma unroll
    for (int nf = 0; nf < 4; nf++)
        #pragma unroll
        for (int e = 0; e < 4; e++) o[nf][e] = 0.f;
    float mrow0 = -1e30f, mrow1 = -1e30f, lrow0 = 0.f, lrow1 = 0.f;

    const float4* K4 = (const float4*)K;
    const float4* V4 = (const float4*)V;
    int srow = tid >> 2;
    int sc4  = tid & 3;

    for (int kt = 0; kt < 8; kt++) {
        int buf = kt & 1;
        #pragma unroll
        for (int i = 0; i < 2; i++) {
            int c4 = sc4 + i * 4;
            size_t gidx = ((size_t)(kt * 64 + srow) * 8192 + base) / 4 + c4;
            float4 kv = K4[gidx];
            float4 vv = V4[gidx];
            split_store4(&Kh[buf][srow * LDSR + c4 * 4], &Kl[buf][srow * LDSR + c4 * 4], kv);
            split_store4(&Vh[buf][srow * LDSR + c4 * 4], &Vl[buf][srow * LDSR + c4 * 4], vv);
        }
        __syncthreads();

        float s[8][4];
        #pragma unroll
        for (int nf = 0; nf < 8; nf++) {
            s[nf][0] = s[nf][1] = s[nf][2] = s[nf][3] = 0.f;
        }
        #pragma unroll
        for (int kf = 0; kf < 2; kf++) {
            uint32_t bh[8][2], bl[8][2];
            #pragma unroll
            for (int nf = 0; nf < 8; nf++) {
                const __nv_bfloat16* pk = &Kh[buf][(nf * 8 + (al16 & 7)) * LDSR + (al16 >> 3) * 8 + kf * 16];
                const __nv_bfloat16* pl = &Kl[buf][(nf * 8 + (al16 & 7)) * LDSR + (al16 >> 3) * 8 + kf * 16];
                ldsm_x2(bh[nf], pk);
                ldsm_x2(bl[nf], pl);
            }
            #pragma unroll
            for (int nf = 0; nf < 8; nf++)
                mma_bf16(s[nf], qh[kf], bh[nf]);
            #pragma unroll
            for (int nf = 0; nf < 8; nf++)
                mma_bf16(s[nf], qh[kf], bl[nf]);
            #pragma unroll
            for (int nf = 0; nf < 8; nf++)
                mma_bf16(s[nf], ql[kf], bh[nf]);
        }

        float t0 = -1e30f, t1 = -1e30f;
        #pragma unroll
        for (int nf = 0; nf < 8; nf++) {
            t0 = fmaxf(t0, fmaxf(s[nf][0], s[nf][1]));
            t1 = fmaxf(t1, fmaxf(s[nf][2], s[nf][3]));
        }
        t0 = fmaxf(t0, __shfl_xor_sync(0xffffffffu, t0, 1));
        t0 = fmaxf(t0, __shfl_xor_sync(0xffffffffu, t0, 2));
        t1 = fmaxf(t1, __shfl_xor_sync(0xffffffffu, t1, 1));
        t1 = fmaxf(t1, __shfl_xor_sync(0xffffffffu, t1, 2));
        float mn0 = fmaxf(mrow0, t0), mn1 = fmaxf(mrow1, t1);
        float corr0 = __expf(mrow0 - mn0), corr1 = __expf(mrow1 - mn1);

        float rs0 = 0.f, rs1 = 0.f;
        #pragma unroll
        for (int nf = 0; nf < 8; nf++) {
            s[nf][0] = __expf(s[nf][0] - mn0); rs0 += s[nf][0];
            s[nf][1] = __expf(s[nf][1] - mn0); rs0 += s[nf][1];
            s[nf][2] = __expf(s[nf][2] - mn1); rs1 += s[nf][2];
            s[nf][3] = __expf(s[nf][3] - mn1); rs1 += s[nf][3];
        }
        rs0 += __shfl_xor_sync(0xffffffffu, rs0, 1);
        rs0 += __shfl_xor_sync(0xffffffffu, rs0, 2);
        rs1 += __shfl_xor_sync(0xffffffffu, rs1, 1);
        rs1 += __shfl_xor_sync(0xffffffffu, rs1, 2);
        lrow0 = lrow0 * corr0 + rs0;
        lrow1 = lrow1 * corr1 + rs1;
        mrow0 = mn0; mrow1 = mn1;

        #pragma unroll
        for (int nf = 0; nf < 4; nf++) {
            o[nf][0] *= corr0; o[nf][1] *= corr0;
            o[nf][2] *= corr1; o[nf][3] *= corr1;
        }

        #pragma unroll
        for (int kg = 0; kg < 4; kg++) {
            uint32_t ph[4], pl2[4];
            pack_split(s[2 * kg][0],     s[2 * kg][1],     &ph[0], &pl2[0]);
            pack_split(s[2 * kg][2],     s[2 * kg][3],     &ph[1], &pl2[1]);
            pack_split(s[2 * kg + 1][0], s[2 * kg + 1][1], &ph[2], &pl2[2]);
            pack_split(s[2 * kg + 1][2], s[2 * kg + 1][3], &ph[3], &pl2[3]);
            uint32_t vbh[4][2], vbl[4][2];
            #pragma unroll
            for (int nf = 0; nf < 4; nf++) {
                ldsm_x2_trans(vbh[nf], &Vh[buf][(kg * 16 + al16) * LDSR + nf * 8]);
                ldsm_x2_trans(vbl[nf], &Vl[buf][(kg * 16 + al16) * LDSR + nf * 8]);
            }
            #pragma unroll
            for (int nf = 0; nf < 4; nf++)
                mma_bf16(o[nf], ph, vbh[nf]);
            #pragma unroll
            for (int nf = 0; nf < 4; nf++)
                mma_bf16(o[nf], ph, vbl[nf]);
            #pragma unroll
            for (int nf = 0; nf < 4; nf++)
                mma_bf16(o[nf], pl2, vbh[nf]);
        }
    }

    float inv0 = 1.f / lrow0, inv1 = 1.f / lrow1;
    #pragma unroll
    for (int nf = 0; nf < 4; nf++) {
        int col = nf * 8 + cq;
        float2 o0 = make_float2(o[nf][0] * inv0, o[nf][1] * inv0);
        float2 o1 = make_float2(o[nf][2] * inv1, o[nf][3] * inv1);
        *(float2*)&O[(size_t)(l0 + r) * 8192 + base + col]     = o0;
        *(float2*)&O[(size_t)(l0 + r + 8) * 8192 + base + col] = o1;
    }
}

// ---------------------------------------------------------------------------
// Scatter: short token layout -> output [n,c,t,h,w]
// grid (16, 64, 4) block (32, 8)
// ---------------------------------------------------------------------------
__global__ void scatter_out(const float* __restrict__ src, float* __restrict__ out) {
    int ct = blockIdx.x >> 1, xt = blockIdx.x & 1;
    int y  = blockIdx.y;
    int nn = blockIdx.z >> 1, t = blockIdx.z & 1;
    int c0 = ct * 32, x0 = xt * 32;
    int bh = y >> 4, ih = y & 15;
    __shared__ float sm[32][33];
    int tx = threadIdx.x, ty = threadIdx.y;
    #pragma unroll
    for (int i = 0; i < 4; i++) {
        int xi = ty + i * 8;
        int x = x0 + xi;
        int bw = x >> 4, iw = x & 15;
        int s  = t * 256 + ih * 16 + iw;
        int b2 = nn * 16 + bh * 4 + bw;
        int token2 = s * 32 + b2;
        sm[tx][xi] = src[(size_t)token2 * CDIM + c0 + tx];
    }
    __syncthreads();
    #pragma unroll
    for (int i = 0; i < 4; i++) {
        int ci = ty + i * 8;
        out[((size_t)(nn * CDIM + c0 + ci) * 2 + t) * 4096 + (size_t)y * 64 + x0 + tx] = sm[ci][tx];
    }
}

// ---------------------------------------------------------------------------
extern "C" void kernel_launch(void* const* d_in, const int* in_sizes, int n_in,
                              void* d_out, int out_size) {
    (void)in_sizes; (void)n_in; (void)out_size;
    const float* q      = (const float*)d_in[0];
    const float* k      = (const float*)d_in[1];
    const float* v      = (const float*)d_in[2];
    const float* pos    = (const float*)d_in[3];
    const float* wl_in  = (const float*)d_in[4];
    const float* bl_in  = (const float*)d_in[5];
    const float* wl_out = (const float*)d_in[6];
    const float* bl_out = (const float*)d_in[7];
    const float* ws_in  = (const float*)d_in[8];
    const float* bs_in  = (const float*)d_in[9];
    const float* ws_out = (const float*)d_in[10];
    const float* bs_out = (const float*)d_in[11];
    float* out = (float*)d_out;

    float *px0, *px1, *px2, *pq, *pk, *pv, *po, *pm;
    cudaGetSymbolAddress((void**)&px0, g_x0);
    cudaGetSymbolAddress((void**)&px1, g_x1);
    cudaGetSymbolAddress((void**)&px2, g_x2);
    cudaGetSymbolAddress((void**)&pq,  g_qb);
    cudaGetSymbolAddress((void**)&pk,  g_kb);
    cudaGetSymbolAddress((void**)&pv,  g_vb);
    cudaGetSymbolAddress((void**)&po,  g_ob);
    cudaGetSymbolAddress((void**)&pm,  g_mb);

    const int GSM_BYTES = GSM_ELEMS * 2;   // 81920
    static bool attr_set = false;
    if (!attr_set) {
        cudaFuncSetAttribute(gemm_nt_tc, cudaFuncAttributeMaxDynamicSharedMemorySize,
                             GSM_BYTES);
        attr_set = true;
    }

    dim3 gGather(16, 64, 4), bGather(32, 8);
    dim3 gGemm3(2, 128, 3);
    dim3 gGemm1(2, 128, 1);
    dim3 gAttn1(512, 8);
    dim3 gAttn2(4, 8, 32);

    // Phase 1: gather to long layout (+pos)
    gather_long<<<gGather, bGather>>>(q, k, v, pos);

    // Phase 2: MHA1 input projections — ONE fused launch (z selects Q/K/V)
    gemm_nt_tc<<<gGemm3, 512, GSM_BYTES>>>(px0, px1, px2, wl_in, bl_in, pq, pk, pv);

    // Phase 3: long attention
    attn1<<<gAttn1, 32>>>(pq, pk, pv, po);

    // Phase 4: MHA1 output projection
    gemm_nt_tc<<<gGemm1, 512, GSM_BYTES>>>(po, po, po, wl_out, bl_out, pm, pm, pm);

    // Phase 5: permute long -> short, add pos
    reindex_short<<<TOK, 64>>>();

    // Phase 6: MHA2 input projections — ONE fused launch (Q,K share x0)
    gemm_nt_tc<<<gGemm3, 512, GSM_BYTES>>>(px0, px0, px2, ws_in, bs_in, pq, pk, pv);

    // Phase 7: short attention (tensor-core flash, double-buffered)
    attn2_tc<<<gAttn2, 256>>>(pq, pk, pv, po);

    // Phase 8: MHA2 output projection + scatter to output layout
    gemm_nt_tc<<<gGemm1, 512, GSM_BYTES>>>(po, po, po, ws_out, bs_out, pm, pm, pm);
    scatter_out<<<gGather, bGather>>>(pm, out);
}

// round 15
// speedup vs baseline: 1.0323x; 1.0323x over previous
#include <cuda_runtime.h>
#include <cuda_bf16.h>
#include <cstdint>

// Problem constants
#define TOK   16384
#define CDIM  256
#define NHEAD 8
#define DHEAD 32
#define SCALE 0.17677669529663687f  // 1/sqrt(32)

// Scratch (static device globals — allocation-free per harness rules)
__device__ float g_x0[TOK * CDIM];
__device__ float g_x1[TOK * CDIM];
__device__ float g_x2[TOK * CDIM];
__device__ float g_p [TOK * CDIM];
__device__ float g_qb[TOK * CDIM];
__device__ float g_kb[TOK * CDIM];
__device__ float g_vb[TOK * CDIM];
__device__ float g_ob[TOK * CDIM];
__device__ float g_mb[TOK * CDIM];

// ---------------------------------------------------------------------------
// Common MMA helpers
// ---------------------------------------------------------------------------
#define LDSR 40   // padded smem row stride in bf16 (80B: ldmatrix conflict-free)

__device__ __forceinline__ void mma_bf16(float* d, const uint32_t* a, const uint32_t* b) {
    asm volatile(
        "mma.sync.aligned.m16n8k16.row.col.f32.bf16.bf16.f32 "
        "{%0,%1,%2,%3}, {%4,%5,%6,%7}, {%8,%9}, {%0,%1,%2,%3};"
        : "+f"(d[0]), "+f"(d[1]), "+f"(d[2]), "+f"(d[3])
        : "r"(a[0]), "r"(a[1]), "r"(a[2]), "r"(a[3]), "r"(b[0]), "r"(b[1]));
}

__device__ __forceinline__ void ldsm_x4(uint32_t* r, const __nv_bfloat16* p) {
    uint32_t addr = (uint32_t)__cvta_generic_to_shared(p);
    asm volatile("ldmatrix.sync.aligned.m8n8.x4.shared.b16 {%0,%1,%2,%3}, [%4];"
                 : "=r"(r[0]), "=r"(r[1]), "=r"(r[2]), "=r"(r[3]) : "r"(addr));
}

__device__ __forceinline__ void ldsm_x2(uint32_t* r, const __nv_bfloat16* p) {
    uint32_t addr = (uint32_t)__cvta_generic_to_shared(p);
    asm volatile("ldmatrix.sync.aligned.m8n8.x2.shared.b16 {%0,%1}, [%2];"
                 : "=r"(r[0]), "=r"(r[1]) : "r"(addr));
}

__device__ __forceinline__ void ldsm_x2_trans(uint32_t* r, const __nv_bfloat16* p) {
    uint32_t addr = (uint32_t)__cvta_generic_to_shared(p);
    asm volatile("ldmatrix.sync.aligned.m8n8.x2.trans.shared.b16 {%0,%1}, [%2];"
                 : "=r"(r[0]), "=r"(r[1]) : "r"(addr));
}

// Truncation split: hi = top-16 bits of fp32 (packed via PRMT), lo = rn(x - hi).
__device__ __forceinline__ void pack_split(float x, float y, uint32_t* hi, uint32_t* lo) {
    uint32_t ux = __float_as_uint(x), uy = __float_as_uint(y);
    *hi = __byte_perm(ux, uy, 0x7632);
    float lx = x - __uint_as_float(ux & 0xFFFF0000u);
    float ly = y - __uint_as_float(uy & 0xFFFF0000u);
    __nv_bfloat162 lp = __floats2bfloat162_rn(lx, ly);
    *lo = *(uint32_t*)&lp;
}

// float4 (4 consecutive k) -> 2 packed hi words + 2 packed lo words, STS.64.
__device__ __forceinline__ void split_store4(__nv_bfloat16* hp, __nv_bfloat16* lp, float4 v) {
    uint32_t h01, h23, l01, l23;
    pack_split(v.x, v.y, &h01, &l01);
    pack_split(v.z, v.w, &h23, &l23);
    uint2 hw; hw.x = h01; hw.y = h23;
    uint2 lw; lw.x = l01; lw.y = l23;
    *(uint2*)hp = hw;
    *(uint2*)lp = lw;
}

// ---------------------------------------------------------------------------
// Gather: [n,c,t,h,w] -> long token layout [token= l*512+b, c]
// ---------------------------------------------------------------------------
__global__ void gather_long(const float* __restrict__ q, const float* __restrict__ k,
                            const float* __restrict__ v, const float* __restrict__ p) {
    int ct = blockIdx.x >> 1, xt = blockIdx.x & 1;
    int y  = blockIdx.y;
    int nn = blockIdx.z >> 1, t = blockIdx.z & 1;
    int c0 = ct * 32, x0 = xt * 32;
    __shared__ float sq[32][33], sk[32][33], sv[32][33], sp[32][33];
    int tx = threadIdx.x, ty = threadIdx.y;
    #pragma unroll
    for (int i = 0; i < 4; i++) {
        int ci = ty + i * 8;
        size_t idx = ((size_t)(nn * CDIM + c0 + ci) * 2 + t) * 4096 + (size_t)y * 64 + x0 + tx;
        float pv = p[idx];
        sq[ci][tx] = q[idx] + pv;
        sk[ci][tx] = k[idx] + pv;
        sv[ci][tx] = v[idx];
        sp[ci][tx] = pv;
    }
    __syncthreads();
    int bh = y >> 4, ih = y & 15;
    #pragma unroll
    for (int i = 0; i < 4; i++) {
        int xi = ty + i * 8;
        int x = x0 + xi;
        int bw = x >> 4, iw = x & 15;
        int token = (t * 16 + bh * 4 + bw) * 512 + nn * 256 + ih * 16 + iw;
        size_t o = (size_t)token * CDIM + c0 + tx;
        g_x0[o] = sq[tx][xi];
        g_x1[o] = sk[tx][xi];
        g_x2[o] = sv[tx][xi];
        g_p [o] = sp[tx][xi];
    }
}

// ---------------------------------------------------------------------------
// Tensor-core GEMM (R12 proven): truncation-split bf16, double-buffered smem,
// STS.64 staging (lcol4 map), B frags via ldsm_x4, z-fused.
// grid (4, 128, nz)  block (256)
// ---------------------------------------------------------------------------
__global__ __launch_bounds__(256) void gemm_nt_tc(const float* __restrict__ X0,
                                                  const float* __restrict__ X1,
                                                  const float* __restrict__ X2,
                                                  const float* __restrict__ W0,
                                                  const float* __restrict__ bias0,
                                                  float* __restrict__ Y0,
                                                  float* __restrict__ Y1,
                                                  float* __restrict__ Y2) {
    __shared__ __nv_bfloat16 As_hi[2][128 * LDSR], As_lo[2][128 * LDSR];
    __shared__ __nv_bfloat16 Bs_hi[2][64 * LDSR],  Bs_lo[2][64 * LDSR];

    int bz = blockIdx.z;
    const float* X = (bz == 0) ? X0 : ((bz == 1) ? X1 : X2);
    float*       Y = (bz == 0) ? Y0 : ((bz == 1) ? Y1 : Y2);
    const float* Wm   = W0 + (size_t)bz * 65536;
    const float* bias = bias0 + bz * 256;

    int tid  = threadIdx.x;
    int warp = tid >> 5, lane = tid & 31;
    int m0 = blockIdx.y * 128, n0 = blockIdx.x * 64;
    int wm = (warp >> 1) * 32;
    int wn = (warp & 1) * 32;

    float acc[2][4][4];
    #pragma unroll
    for (int mi = 0; mi < 2; mi++)
        #pragma unroll
        for (int ni = 0; ni < 4; ni++)
            #pragma unroll
            for (int e = 0; e < 4; e++) acc[mi][ni][e] = 0.f;

    const float4* X4 = (const float4*)X;
    const float4* W4 = (const float4*)Wm;
    int lrow  = tid >> 3;
    int lcol4 = tid & 7;

    int al16 = lane & 15;
    int offA = (wm + al16) * LDSR + (lane >> 4) * 8;
    int offB = (wn + al16) * LDSR + (lane >> 4) * 8;

    float4 xa[4], wb[2];
    #pragma unroll
    for (int i = 0; i < 4; i++)
        xa[i] = X4[(size_t)(m0 + lrow + i * 32) * 64 + lcol4];
    #pragma unroll
    for (int i = 0; i < 2; i++)
        wb[i] = W4[(size_t)(n0 + lrow + i * 32) * 64 + lcol4];

    for (int kt = 0; kt < 8; kt++) {
        int buf = kt & 1;
        #pragma unroll
        for (int i = 0; i < 4; i++) {
            int r = lrow + i * 32;
            split_store4(&As_hi[buf][r * LDSR + lcol4 * 4],
                         &As_lo[buf][r * LDSR + lcol4 * 4], xa[i]);
        }
        #pragma unroll
        for (int i = 0; i < 2; i++) {
            int r = lrow + i * 32;
            split_store4(&Bs_hi[buf][r * LDSR + lcol4 * 4],
                         &Bs_lo[buf][r * LDSR + lcol4 * 4], wb[i]);
        }
        __syncthreads();

        if (kt < 7) {
            #pragma unroll
            for (int i = 0; i < 4; i++)
                xa[i] = X4[(size_t)(m0 + lrow + i * 32) * 64 + (kt + 1) * 8 + lcol4];
            #pragma unroll
            for (int i = 0; i < 2; i++)
                wb[i] = W4[(size_t)(n0 + lrow + i * 32) * 64 + (kt + 1) * 8 + lcol4];
        }

        const __nv_bfloat16* pa_hi0 = &As_hi[buf][offA];
        const __nv_bfloat16* pa_lo0 = &As_lo[buf][offA];
        const __nv_bfloat16* pb_hi0 = &Bs_hi[buf][offB];
        const __nv_bfloat16* pb_lo0 = &Bs_lo[buf][offB];

        #pragma unroll
        for (int kk = 0; kk < 2; kk++) {
            int ko = kk * 16;
            uint32_t ah[2][4], al[2][4];
            #pragma unroll
            for (int mi = 0; mi < 2; mi++) {
                ldsm_x4(ah[mi], pa_hi0 + mi * 16 * LDSR + ko);
                ldsm_x4(al[mi], pa_lo0 + mi * 16 * LDSR + ko);
            }
            uint32_t bh[4][2], bl[4][2];
            #pragma unroll
            for (int ni2 = 0; ni2 < 2; ni2++) {
                uint32_t r4[4];
                ldsm_x4(r4, pb_hi0 + ni2 * 16 * LDSR + ko);
                bh[2 * ni2][0] = r4[0]; bh[2 * ni2][1] = r4[2];
                bh[2 * ni2 + 1][0] = r4[1]; bh[2 * ni2 + 1][1] = r4[3];
                ldsm_x4(r4, pb_lo0 + ni2 * 16 * LDSR + ko);
                bl[2 * ni2][0] = r4[0]; bl[2 * ni2][1] = r4[2];
                bl[2 * ni2 + 1][0] = r4[1]; bl[2 * ni2 + 1][1] = r4[3];
            }
            #pragma unroll
            for (int mi = 0; mi < 2; mi++)
                #pragma unroll
                for (int ni = 0; ni < 4; ni++) {
                    mma_bf16(acc[mi][ni], ah[mi], bh[ni]);
                    mma_bf16(acc[mi][ni], ah[mi], bl[ni]);
                    mma_bf16(acc[mi][ni], al[mi], bh[ni]);
                }
        }
    }

    int cr = lane >> 2;
    int cc = (lane & 3) * 2;
    #pragma unroll
    for (int mi = 0; mi < 2; mi++) {
        #pragma unroll
        for (int ni = 0; ni < 4; ni++) {
            int col = n0 + wn + ni * 8 + cc;
            float b0 = bias[col], b1 = bias[col + 1];
            int row0 = m0 + wm + mi * 16 + cr;
            float2 o0 = make_float2(acc[mi][ni][0] + b0, acc[mi][ni][1] + b1);
            float2 o1 = make_float2(acc[mi][ni][2] + b0, acc[mi][ni][3] + b1);
            *(float2*)&Y[(size_t)row0 * CDIM + col]       = o0;
            *(float2*)&Y[(size_t)(row0 + 8) * CDIM + col] = o1;
        }
    }
}

// ---------------------------------------------------------------------------
// Attention #1 (long): all 8 heads of one b in one 256-thread block.
// Warp = head; per-warp math identical to the proven per-head version.
// K/V staged with fully-coalesced 1KB rows. grid (512) block (32, 8)
// dyn smem 64KB (3 CTAs/SM)
// ---------------------------------------------------------------------------
__global__ __launch_bounds__(256) void attn1(const float* __restrict__ Q,
                                             const float* __restrict__ K,
                                             const float* __restrict__ V,
                                             float* __restrict__ O) {
    extern __shared__ float a1sm[];
    float* Ks = a1sm;              // [32][256]
    float* Vs = a1sm + 32 * 256;   // [32][256]
    int b = blockIdx.x;
    int tid = threadIdx.x, h = threadIdx.y;
    int t256 = h * 32 + tid;
    for (int r = 0; r < 32; r++) {
        size_t idx = (size_t)r * 131072 + (size_t)b * CDIM + t256;
        Ks[r * 256 + t256] = K[idx];
        Vs[r * 256 + t256] = V[idx];
    }
    __syncthreads();

    size_t base = (size_t)b * CDIM + h * DHEAD;
    float q[32];
    const float4* q4 = (const float4*)(Q + (size_t)tid * 131072 + base);
    #pragma unroll
    for (int d4 = 0; d4 < 8; d4++) {
        float4 qq = q4[d4];
        q[d4 * 4 + 0] = qq.x * SCALE; q[d4 * 4 + 1] = qq.y * SCALE;
        q[d4 * 4 + 2] = qq.z * SCALE; q[d4 * 4 + 3] = qq.w * SCALE;
    }
    float s[32];
    float m = -1e30f;
    #pragma unroll
    for (int j = 0; j < 32; j++) {
        const float4* kr = (const float4*)&Ks[j * 256 + h * DHEAD];
        float a = 0.f;
        #pragma unroll
        for (int d4 = 0; d4 < 8; d4++) {
            float4 kv = kr[d4];
            a += q[d4 * 4 + 0] * kv.x + q[d4 * 4 + 1] * kv.y
               + q[d4 * 4 + 2] * kv.z + q[d4 * 4 + 3] * kv.w;
        }
        s[j] = a;
        m = fmaxf(m, a);
    }
    float lsum = 0.f;
    #pragma unroll
    for (int j = 0; j < 32; j++) { s[j] = __expf(s[j] - m); lsum += s[j]; }
    float acc[32];
    #pragma unroll
    for (int d = 0; d < 32; d++) acc[d] = 0.f;
    #pragma unroll
    for (int j = 0; j < 32; j++) {
        const float4* vr = (const float4*)&Vs[j * 256 + h * DHEAD];
        float pj = s[j];
        #pragma unroll
        for (int d4 = 0; d4 < 8; d4++) {
            float4 vv = vr[d4];
            acc[d4 * 4 + 0] += pj * vv.x; acc[d4 * 4 + 1] += pj * vv.y;
            acc[d4 * 4 + 2] += pj * vv.z; acc[d4 * 4 + 3] += pj * vv.w;
        }
    }
    float inv = 1.f / lsum;
    float4* o4 = (float4*)(O + (size_t)tid * 131072 + base);
    #pragma unroll
    for (int d4 = 0; d4 < 8; d4++) {
        float4 oo;
        oo.x = acc[d4 * 4 + 0] * inv; oo.y = acc[d4 * 4 + 1] * inv;
        oo.z = acc[d4 * 4 + 2] * inv; oo.w = acc[d4 * 4 + 3] * inv;
        o4[d4] = oo;
    }
}

// ---------------------------------------------------------------------------
// Re-index long -> short, add pos (float4 vectorized)
// grid (16384) block (64)
// ---------------------------------------------------------------------------
__global__ void reindex_short() {
    int token2 = blockIdx.x;
    int s = token2 >> 5, b2 = token2 & 31;
    int t = s >> 8, rem = s & 255, ih = rem >> 4, iw = rem & 15;
    int nn = b2 >> 4, rr = b2 & 15, bh = rr >> 2, bw = rr & 3;
    int token = (t * 16 + bh * 4 + bw) * 512 + nn * 256 + ih * 16 + iw;
    int c4 = threadIdx.x;
    size_t si = (size_t)token * 64 + c4;
    size_t di = (size_t)token2 * 64 + c4;
    float4 x  = ((const float4*)g_mb)[si];
    float4 pp = ((const float4*)g_p)[si];
    float4 xp = make_float4(x.x + pp.x, x.y + pp.y, x.z + pp.z, x.w + pp.w);
    ((float4*)g_x0)[di] = xp;
    ((float4*)g_x2)[di] = x;
}

// ---------------------------------------------------------------------------
// Attention #2 (short): FA2 on mma.sync, truncation-split bf16, double-
// buffered K/V, one barrier per tile. 512 threads = 16 warps handle 256
// queries per CTA (2 q-tiles): K/V staging traffic halved vs 256-thr version.
// grid (2, 8, 32) block (512)
// ---------------------------------------------------------------------------
__global__ __launch_bounds__(512) void attn2_tc(const float* __restrict__ Q,
                                                const float* __restrict__ K,
                                                const float* __restrict__ V,
                                                float* __restrict__ O) {
    int qt = blockIdx.x, h = blockIdx.y, b2 = blockIdx.z;
    size_t base = (size_t)b2 * CDIM + h * DHEAD;
    __shared__ __nv_bfloat16 Kh[2][64 * LDSR], Kl[2][64 * LDSR];
    __shared__ __nv_bfloat16 Vh[2][64 * LDSR], Vl[2][64 * LDSR];

    int tid = threadIdx.x, warp = tid >> 5, lane = tid & 31;
    int al16 = lane & 15;
    int r  = lane >> 2;
    int cq = (lane & 3) * 2;
    int l0 = qt * 256 + warp * 16;

    uint32_t qh[2][4], ql[2][4];
    #pragma unroll
    for (int kf = 0; kf < 2; kf++) {
        #pragma unroll
        for (int half = 0; half < 2; half++) {
            int col = kf * 16 + half * 8 + cq;
            float2 v0 = *(const float2*)&Q[(size_t)(l0 + r) * 8192 + base + col];
            float2 v1 = *(const float2*)&Q[(size_t)(l0 + r + 8) * 8192 + base + col];
            v0.x *= SCALE; v0.y *= SCALE; v1.x *= SCALE; v1.y *= SCALE;
            pack_split(v0.x, v0.y, &qh[kf][half * 2 + 0], &ql[kf][half * 2 + 0]);
            pack_split(v1.x, v1.y, &qh[kf][half * 2 + 1], &ql[kf][half * 2 + 1]);
        }
    }

    float o[4][4];
    #pragma unroll
    for (int nf = 0; nf < 4; nf++)
        #pragma unroll
        for (int e = 0; e < 4; e++) o[nf][e] = 0.f;
    float mrow0 = -1e30f, mrow1 = -1e30f, lrow0 = 0.f, lrow1 = 0.f;

    const float4* K4 = (const float4*)K;
    const float4* V4 = (const float4*)V;
    int srow = tid >> 3;   // 0..63
    int sc4  = tid & 7;    // 0..7

    for (int kt = 0; kt < 8; kt++) {
        int buf = kt & 1;
        // Stage tile kt into buf (one float4 of K and V per thread).
        {
            size_t gidx = ((size_t)(kt * 64 + srow) * 8192 + base) / 4 + sc4;
            float4 kv = K4[gidx];
            float4 vv = V4[gidx];
            split_store4(&Kh[buf][srow * LDSR + sc4 * 4], &Kl[buf][srow * LDSR + sc4 * 4], kv);
            split_store4(&Vh[buf][srow * LDSR + sc4 * 4], &Vl[buf][srow * LDSR + sc4 * 4], vv);
        }
        __syncthreads();

        float s[8][4];
        #pragma unroll
        for (int nf = 0; nf < 8; nf++) {
            s[nf][0] = s[nf][1] = s[nf][2] = s[nf][3] = 0.f;
        }
        #pragma unroll
        for (int kf = 0; kf < 2; kf++) {
            uint32_t bh[8][2], bl[8][2];
            #pragma unroll
            for (int nf = 0; nf < 8; nf++) {
                const __nv_bfloat16* pk = &Kh[buf][(nf * 8 + (al16 & 7)) * LDSR + (al16 >> 3) * 8 + kf * 16];
                const __nv_bfloat16* pl = &Kl[buf][(nf * 8 + (al16 & 7)) * LDSR + (al16 >> 3) * 8 + kf * 16];
                ldsm_x2(bh[nf], pk);
                ldsm_x2(bl[nf], pl);
            }
            #pragma unroll
            for (int nf = 0; nf < 8; nf++)
                mma_bf16(s[nf], qh[kf], bh[nf]);
            #pragma unroll
            for (int nf = 0; nf < 8; nf++)
                mma_bf16(s[nf], qh[kf], bl[nf]);
            #pragma unroll
            for (int nf = 0; nf < 8; nf++)
                mma_bf16(s[nf], ql[kf], bh[nf]);
        }

        float t0 = -1e30f, t1 = -1e30f;
        #pragma unroll
        for (int nf = 0; nf < 8; nf++) {
            t0 = fmaxf(t0, fmaxf(s[nf][0], s[nf][1]));
            t1 = fmaxf(t1, fmaxf(s[nf][2], s[nf][3]));
        }
        t0 = fmaxf(t0, __shfl_xor_sync(0xffffffffu, t0, 1));
        t0 = fmaxf(t0, __shfl_xor_sync(0xffffffffu, t0, 2));
        t1 = fmaxf(t1, __shfl_xor_sync(0xffffffffu, t1, 1));
        t1 = fmaxf(t1, __shfl_xor_sync(0xffffffffu, t1, 2));
        float mn0 = fmaxf(mrow0, t0), mn1 = fmaxf(mrow1, t1);
        float corr0 = __expf(mrow0 - mn0), corr1 = __expf(mrow1 - mn1);

        float rs0 = 0.f, rs1 = 0.f;
        #pragma unroll
        for (int nf = 0; nf < 8; nf++) {
            s[nf][0] = __expf(s[nf][0] - mn0); rs0 += s[nf][0];
            s[nf][1] = __expf(s[nf][1] - mn0); rs0 += s[nf][1];
            s[nf][2] = __expf(s[nf][2] - mn1); rs1 += s[nf][2];
            s[nf][3] = __expf(s[nf][3] - mn1); rs1 += s[nf][3];
        }
        rs0 += __shfl_xor_sync(0xffffffffu, rs0, 1);
        rs0 += __shfl_xor_sync(0xffffffffu, rs0, 2);
        rs1 += __shfl_xor_sync(0xffffffffu, rs1, 1);
        rs1 += __shfl_xor_sync(0xffffffffu, rs1, 2);
        lrow0 = lrow0 * corr0 + rs0;
        lrow1 = lrow1 * corr1 + rs1;
        mrow0 = mn0; mrow1 = mn1;

        #pragma unroll
        for (int nf = 0; nf < 4; nf++) {
            o[nf][0] *= corr0; o[nf][1] *= corr0;
            o[nf][2] *= corr1; o[nf][3] *= corr1;
        }

        #pragma unroll
        for (int kg = 0; kg < 4; kg++) {
            uint32_t ph[4], pl2[4];
            pack_split(s[2 * kg][0],     s[2 * kg][1],     &ph[0], &pl2[0]);
            pack_split(s[2 * kg][2],     s[2 * kg][3],     &ph[1], &pl2[1]);
            pack_split(s[2 * kg + 1][0], s[2 * kg + 1][1], &ph[2], &pl2[2]);
            pack_split(s[2 * kg + 1][2], s[2 * kg + 1][3], &ph[3], &pl2[3]);
            uint32_t vbh[4][2], vbl[4][2];
            #pragma unroll
            for (int nf = 0; nf < 4; nf++) {
                ldsm_x2_trans(vbh[nf], &Vh[buf][(kg * 16 + al16) * LDSR + nf * 8]);
                ldsm_x2_trans(vbl[nf], &Vl[buf][(kg * 16 + al16) * LDSR + nf * 8]);
            }
            #pragma unroll
            for (int nf = 0; nf < 4; nf++)
                mma_bf16(o[nf], ph, vbh[nf]);
            #pragma unroll
            for (int nf = 0; nf < 4; nf++)
                mma_bf16(o[nf], ph, vbl[nf]);
            #pragma unroll
            for (int nf = 0; nf < 4; nf++)
                mma_bf16(o[nf], pl2, vbh[nf]);
        }
    }

    float inv0 = 1.f / lrow0, inv1 = 1.f / lrow1;
    #pragma unroll
    for (int nf = 0; nf < 4; nf++) {
        int col = nf * 8 + cq;
        float2 o0 = make_float2(o[nf][0] * inv0, o[nf][1] * inv0);
        float2 o1 = make_float2(o[nf][2] * inv1, o[nf][3] * inv1);
        *(float2*)&O[(size_t)(l0 + r) * 8192 + base + col]     = o0;
        *(float2*)&O[(size_t)(l0 + r + 8) * 8192 + base + col] = o1;
    }
}

// ---------------------------------------------------------------------------
// Scatter: short token layout -> output [n,c,t,h,w]
// grid (16, 64, 4) block (32, 8)
// ---------------------------------------------------------------------------
__global__ void scatter_out(const float* __restrict__ src, float* __restrict__ out) {
    int ct = blockIdx.x >> 1, xt = blockIdx.x & 1;
    int y  = blockIdx.y;
    int nn = blockIdx.z >> 1, t = blockIdx.z & 1;
    int c0 = ct * 32, x0 = xt * 32;
    int bh = y >> 4, ih = y & 15;
    __shared__ float sm[32][33];
    int tx = threadIdx.x, ty = threadIdx.y;
    #pragma unroll
    for (int i = 0; i < 4; i++) {
        int xi = ty + i * 8;
        int x = x0 + xi;
        int bw = x >> 4, iw = x & 15;
        int s  = t * 256 + ih * 16 + iw;
        int b2 = nn * 16 + bh * 4 + bw;
        int token2 = s * 32 + b2;
        sm[tx][xi] = src[(size_t)token2 * CDIM + c0 + tx];
    }
    __syncthreads();
    #pragma unroll
    for (int i = 0; i < 4; i++) {
        int ci = ty + i * 8;
        out[((size_t)(nn * CDIM + c0 + ci) * 2 + t) * 4096 + (size_t)y * 64 + x0 + tx] = sm[ci][tx];
    }
}

// ---------------------------------------------------------------------------
extern "C" void kernel_launch(void* const* d_in, const int* in_sizes, int n_in,
                              void* d_out, int out_size) {
    (void)in_sizes; (void)n_in; (void)out_size;
    const float* q      = (const float*)d_in[0];
    const float* k      = (const float*)d_in[1];
    const float* v      = (const float*)d_in[2];
    const float* pos    = (const float*)d_in[3];
    const float* wl_in  = (const float*)d_in[4];
    const float* bl_in  = (const float*)d_in[5];
    const float* wl_out = (const float*)d_in[6];
    const float* bl_out = (const float*)d_in[7];
    const float* ws_in  = (const float*)d_in[8];
    const float* bs_in  = (const float*)d_in[9];
    const float* ws_out = (const float*)d_in[10];
    const float* bs_out = (const float*)d_in[11];
    float* out = (float*)d_out;

    float *px0, *px1, *px2, *pq, *pk, *pv, *po, *pm;
    cudaGetSymbolAddress((void**)&px0, g_x0);
    cudaGetSymbolAddress((void**)&px1, g_x1);
    cudaGetSymbolAddress((void**)&px2, g_x2);
    cudaGetSymbolAddress((void**)&pq,  g_qb);
    cudaGetSymbolAddress((void**)&pk,  g_kb);
    cudaGetSymbolAddress((void**)&pv,  g_vb);
    cudaGetSymbolAddress((void**)&po,  g_ob);
    cudaGetSymbolAddress((void**)&pm,  g_mb);

    const int A1_SMEM = 32 * 256 * 2 * (int)sizeof(float);   // 65536
    static bool attr_set = false;
    if (!attr_set) {
        cudaFuncSetAttribute(attn1, cudaFuncAttributeMaxDynamicSharedMemorySize,
                             A1_SMEM);
        attr_set = true;
    }

    dim3 gGather(16, 64, 4), bGather(32, 8);
    dim3 gGemm3(4, 128, 3);
    dim3 gGemm1(4, 128, 1);
    dim3 gAttn1(512), bAttn1(32, 8);
    dim3 gAttn2(2, 8, 32);

    // Phase 1: gather to long layout (+pos)
    gather_long<<<gGather, bGather>>>(q, k, v, pos);

    // Phase 2: MHA1 input projections — ONE fused launch (z selects Q/K/V)
    gemm_nt_tc<<<gGemm3, 256>>>(px0, px1, px2, wl_in, bl_in, pq, pk, pv);

    // Phase 3: long attention (8 heads per block)
    attn1<<<gAttn1, bAttn1, A1_SMEM>>>(pq, pk, pv, po);

    // Phase 4: MHA1 output projection
    gemm_nt_tc<<<gGemm1, 256>>>(po, po, po, wl_out, bl_out, pm, pm, pm);

    // Phase 5: permute long -> short, add pos
    reindex_short<<<TOK, 64>>>();

    // Phase 6: MHA2 input projections — ONE fused launch (Q,K share x0)
    gemm_nt_tc<<<gGemm3, 256>>>(px0, px0, px2, ws_in, bs_in, pq, pk, pv);

    // Phase 7: short attention (512 thr, 2 q-tiles per CTA)
    attn2_tc<<<gAttn2, 512>>>(pq, pk, pv, po);

    // Phase 8: MHA2 output projection + scatter to output layout
    gemm_nt_tc<<<gGemm1, 256>>>(po, po, po, ws_out, bs_out, pm, pm, pm);
    scatter_out<<<gGather, bGather>>>(pm, out);
}

// round 16
// speedup vs baseline: 1.0967x; 1.0623x over previous
#include <cuda_runtime.h>
#include <cuda_bf16.h>
#include <cstdint>

// Problem constants
#define TOK   16384
#define CDIM  256
#define NHEAD 8
#define DHEAD 32
#define SCALE 0.17677669529663687f  // 1/sqrt(32)

// Scratch (static device globals — allocation-free per harness rules)
__device__ float g_x0[TOK * CDIM];
__device__ float g_x1[TOK * CDIM];
__device__ float g_x2[TOK * CDIM];
__device__ float g_p [TOK * CDIM];
__device__ float g_qb[TOK * CDIM];
__device__ float g_kb[TOK * CDIM];
__device__ float g_vb[TOK * CDIM];
__device__ float g_ob[TOK * CDIM];
__device__ float g_mb[TOK * CDIM];

// ---------------------------------------------------------------------------
// Common MMA helpers
// ---------------------------------------------------------------------------
#define LDSR 40   // padded smem row stride in bf16 (80B: ldmatrix conflict-free)

__device__ __forceinline__ void mma_bf16(float* d, const uint32_t* a, const uint32_t* b) {
    asm volatile(
        "mma.sync.aligned.m16n8k16.row.col.f32.bf16.bf16.f32 "
        "{%0,%1,%2,%3}, {%4,%5,%6,%7}, {%8,%9}, {%0,%1,%2,%3};"
        : "+f"(d[0]), "+f"(d[1]), "+f"(d[2]), "+f"(d[3])
        : "r"(a[0]), "r"(a[1]), "r"(a[2]), "r"(a[3]), "r"(b[0]), "r"(b[1]));
}

__device__ __forceinline__ void ldsm_x4(uint32_t* r, const __nv_bfloat16* p) {
    uint32_t addr = (uint32_t)__cvta_generic_to_shared(p);
    asm volatile("ldmatrix.sync.aligned.m8n8.x4.shared.b16 {%0,%1,%2,%3}, [%4];"
                 : "=r"(r[0]), "=r"(r[1]), "=r"(r[2]), "=r"(r[3]) : "r"(addr));
}

__device__ __forceinline__ void ldsm_x2(uint32_t* r, const __nv_bfloat16* p) {
    uint32_t addr = (uint32_t)__cvta_generic_to_shared(p);
    asm volatile("ldmatrix.sync.aligned.m8n8.x2.shared.b16 {%0,%1}, [%2];"
                 : "=r"(r[0]), "=r"(r[1]) : "r"(addr));
}

__device__ __forceinline__ void ldsm_x2_trans(uint32_t* r, const __nv_bfloat16* p) {
    uint32_t addr = (uint32_t)__cvta_generic_to_shared(p);
    asm volatile("ldmatrix.sync.aligned.m8n8.x2.trans.shared.b16 {%0,%1}, [%2];"
                 : "=r"(r[0]), "=r"(r[1]) : "r"(addr));
}

// Truncation split: hi = top-16 bits of fp32 (packed via PRMT), lo = rn(x - hi).
__device__ __forceinline__ void pack_split(float x, float y, uint32_t* hi, uint32_t* lo) {
    uint32_t ux = __float_as_uint(x), uy = __float_as_uint(y);
    *hi = __byte_perm(ux, uy, 0x7632);
    float lx = x - __uint_as_float(ux & 0xFFFF0000u);
    float ly = y - __uint_as_float(uy & 0xFFFF0000u);
    __nv_bfloat162 lp = __floats2bfloat162_rn(lx, ly);
    *lo = *(uint32_t*)&lp;
}

// float4 (4 consecutive k) -> 2 packed hi words + 2 packed lo words, STS.64.
__device__ __forceinline__ void split_store4(__nv_bfloat16* hp, __nv_bfloat16* lp, float4 v) {
    uint32_t h01, h23, l01, l23;
    pack_split(v.x, v.y, &h01, &l01);
    pack_split(v.z, v.w, &h23, &l23);
    uint2 hw; hw.x = h01; hw.y = h23;
    uint2 lw; lw.x = l01; lw.y = l23;
    *(uint2*)hp = hw;
    *(uint2*)lp = lw;
}

// ---------------------------------------------------------------------------
// Gather: [n,c,t,h,w] -> long token layout [token= l*512+b, c]
// ---------------------------------------------------------------------------
__global__ void gather_long(const float* __restrict__ q, const float* __restrict__ k,
                            const float* __restrict__ v, const float* __restrict__ p) {
    int ct = blockIdx.x >> 1, xt = blockIdx.x & 1;
    int y  = blockIdx.y;
    int nn = blockIdx.z >> 1, t = blockIdx.z & 1;
    int c0 = ct * 32, x0 = xt * 32;
    __shared__ float sq[32][33], sk[32][33], sv[32][33], sp[32][33];
    int tx = threadIdx.x, ty = threadIdx.y;
    #pragma unroll
    for (int i = 0; i < 4; i++) {
        int ci = ty + i * 8;
        size_t idx = ((size_t)(nn * CDIM + c0 + ci) * 2 + t) * 4096 + (size_t)y * 64 + x0 + tx;
        float pv = p[idx];
        sq[ci][tx] = q[idx] + pv;
        sk[ci][tx] = k[idx] + pv;
        sv[ci][tx] = v[idx];
        sp[ci][tx] = pv;
    }
    __syncthreads();
    int bh = y >> 4, ih = y & 15;
    #pragma unroll
    for (int i = 0; i < 4; i++) {
        int xi = ty + i * 8;
        int x = x0 + xi;
        int bw = x >> 4, iw = x & 15;
        int token = (t * 16 + bh * 4 + bw) * 512 + nn * 256 + ih * 16 + iw;
        size_t o = (size_t)token * CDIM + c0 + tx;
        g_x0[o] = sq[tx][xi];
        g_x1[o] = sk[tx][xi];
        g_x2[o] = sv[tx][xi];
        g_p [o] = sp[tx][xi];
    }
}

// ---------------------------------------------------------------------------
// Tensor-core GEMM (proven): truncation-split bf16, double-buffered smem,
// STS.64 staging (lcol4 map), B frags via ldsm_x4, z-fused.
// grid (4, 128, nz)  block (256)
// ---------------------------------------------------------------------------
__global__ __launch_bounds__(256) void gemm_nt_tc(const float* __restrict__ X0,
                                                  const float* __restrict__ X1,
                                                  const float* __restrict__ X2,
                                                  const float* __restrict__ W0,
                                                  const float* __restrict__ bias0,
                                                  float* __restrict__ Y0,
                                                  float* __restrict__ Y1,
                                                  float* __restrict__ Y2) {
    __shared__ __nv_bfloat16 As_hi[2][128 * LDSR], As_lo[2][128 * LDSR];
    __shared__ __nv_bfloat16 Bs_hi[2][64 * LDSR],  Bs_lo[2][64 * LDSR];

    int bz = blockIdx.z;
    const float* X = (bz == 0) ? X0 : ((bz == 1) ? X1 : X2);
    float*       Y = (bz == 0) ? Y0 : ((bz == 1) ? Y1 : Y2);
    const float* Wm   = W0 + (size_t)bz * 65536;
    const float* bias = bias0 + bz * 256;

    int tid  = threadIdx.x;
    int warp = tid >> 5, lane = tid & 31;
    int m0 = blockIdx.y * 128, n0 = blockIdx.x * 64;
    int wm = (warp >> 1) * 32;
    int wn = (warp & 1) * 32;

    float acc[2][4][4];
    #pragma unroll
    for (int mi = 0; mi < 2; mi++)
        #pragma unroll
        for (int ni = 0; ni < 4; ni++)
            #pragma unroll
            for (int e = 0; e < 4; e++) acc[mi][ni][e] = 0.f;

    const float4* X4 = (const float4*)X;
    const float4* W4 = (const float4*)Wm;
    int lrow  = tid >> 3;
    int lcol4 = tid & 7;

    int al16 = lane & 15;
    int offA = (wm + al16) * LDSR + (lane >> 4) * 8;
    int offB = (wn + al16) * LDSR + (lane >> 4) * 8;

    float4 xa[4], wb[2];
    #pragma unroll
    for (int i = 0; i < 4; i++)
        xa[i] = X4[(size_t)(m0 + lrow + i * 32) * 64 + lcol4];
    #pragma unroll
    for (int i = 0; i < 2; i++)
        wb[i] = W4[(size_t)(n0 + lrow + i * 32) * 64 + lcol4];

    for (int kt = 0; kt < 8; kt++) {
        int buf = kt & 1;
        #pragma unroll
        for (int i = 0; i < 4; i++) {
            int r = lrow + i * 32;
            split_store4(&As_hi[buf][r * LDSR + lcol4 * 4],
                         &As_lo[buf][r * LDSR + lcol4 * 4], xa[i]);
        }
        #pragma unroll
        for (int i = 0; i < 2; i++) {
            int r = lrow + i * 32;
            split_store4(&Bs_hi[buf][r * LDSR + lcol4 * 4],
                         &Bs_lo[buf][r * LDSR + lcol4 * 4], wb[i]);
        }
        __syncthreads();

        if (kt < 7) {
            #pragma unroll
            for (int i = 0; i < 4; i++)
                xa[i] = X4[(size_t)(m0 + lrow + i * 32) * 64 + (kt + 1) * 8 + lcol4];
            #pragma unroll
            for (int i = 0; i < 2; i++)
                wb[i] = W4[(size_t)(n0 + lrow + i * 32) * 64 + (kt + 1) * 8 + lcol4];
        }

        const __nv_bfloat16* pa_hi0 = &As_hi[buf][offA];
        const __nv_bfloat16* pa_lo0 = &As_lo[buf][offA];
        const __nv_bfloat16* pb_hi0 = &Bs_hi[buf][offB];
        const __nv_bfloat16* pb_lo0 = &Bs_lo[buf][offB];

        #pragma unroll
        for (int kk = 0; kk < 2; kk++) {
            int ko = kk * 16;
            uint32_t ah[2][4], al[2][4];
            #pragma unroll
            for (int mi = 0; mi < 2; mi++) {
                ldsm_x4(ah[mi], pa_hi0 + mi * 16 * LDSR + ko);
                ldsm_x4(al[mi], pa_lo0 + mi * 16 * LDSR + ko);
            }
            uint32_t bh[4][2], bl[4][2];
            #pragma unroll
            for (int ni2 = 0; ni2 < 2; ni2++) {
                uint32_t r4[4];
                ldsm_x4(r4, pb_hi0 + ni2 * 16 * LDSR + ko);
                bh[2 * ni2][0] = r4[0]; bh[2 * ni2][1] = r4[2];
                bh[2 * ni2 + 1][0] = r4[1]; bh[2 * ni2 + 1][1] = r4[3];
                ldsm_x4(r4, pb_lo0 + ni2 * 16 * LDSR + ko);
                bl[2 * ni2][0] = r4[0]; bl[2 * ni2][1] = r4[2];
                bl[2 * ni2 + 1][0] = r4[1]; bl[2 * ni2 + 1][1] = r4[3];
            }
            #pragma unroll
            for (int mi = 0; mi < 2; mi++)
                #pragma unroll
                for (int ni = 0; ni < 4; ni++) {
                    mma_bf16(acc[mi][ni], ah[mi], bh[ni]);
                    mma_bf16(acc[mi][ni], ah[mi], bl[ni]);
                    mma_bf16(acc[mi][ni], al[mi], bh[ni]);
                }
        }
    }

    int cr = lane >> 2;
    int cc = (lane & 3) * 2;
    #pragma unroll
    for (int mi = 0; mi < 2; mi++) {
        #pragma unroll
        for (int ni = 0; ni < 4; ni++) {
            int col = n0 + wn + ni * 8 + cc;
            float b0 = bias[col], b1 = bias[col + 1];
            int row0 = m0 + wm + mi * 16 + cr;
            float2 o0 = make_float2(acc[mi][ni][0] + b0, acc[mi][ni][1] + b1);
            float2 o1 = make_float2(acc[mi][ni][2] + b0, acc[mi][ni][3] + b1);
            *(float2*)&Y[(size_t)row0 * CDIM + col]       = o0;
            *(float2*)&Y[(size_t)(row0 + 8) * CDIM + col] = o1;
        }
    }
}

// ---------------------------------------------------------------------------
// Attention #1 (long): Lq=Lk=32, d=32; one warp per (b,h); thread = query row.
// grid (512, 8) block (32)
// ---------------------------------------------------------------------------
__global__ void attn1(const float* __restrict__ Q, const float* __restrict__ K,
                      const float* __restrict__ V, float* __restrict__ O) {
    int b = blockIdx.x, h = blockIdx.y;
    size_t base = (size_t)b * CDIM + h * DHEAD;
    __shared__ float Ks[32][36], Vs[32][36];
    int tid = threadIdx.x;
    for (int r = 0; r < 32; r++) {
        size_t idx = (size_t)r * 131072 + base + tid;
        Ks[r][tid] = K[idx];
        Vs[r][tid] = V[idx];
    }
    __syncthreads();
    float q[32];
    const float4* q4 = (const float4*)(Q + (size_t)tid * 131072 + base);
    #pragma unroll
    for (int d4 = 0; d4 < 8; d4++) {
        float4 qq = q4[d4];
        q[d4 * 4 + 0] = qq.x * SCALE; q[d4 * 4 + 1] = qq.y * SCALE;
        q[d4 * 4 + 2] = qq.z * SCALE; q[d4 * 4 + 3] = qq.w * SCALE;
    }
    float s[32];
    float m = -1e30f;
    #pragma unroll
    for (int j = 0; j < 32; j++) {
        const float4* kr = (const float4*)Ks[j];
        float a = 0.f;
        #pragma unroll
        for (int d4 = 0; d4 < 8; d4++) {
            float4 kv = kr[d4];
            a += q[d4 * 4 + 0] * kv.x + q[d4 * 4 + 1] * kv.y
               + q[d4 * 4 + 2] * kv.z + q[d4 * 4 + 3] * kv.w;
        }
        s[j] = a;
        m = fmaxf(m, a);
    }
    float lsum = 0.f;
    #pragma unroll
    for (int j = 0; j < 32; j++) { s[j] = __expf(s[j] - m); lsum += s[j]; }
    float acc[32];
    #pragma unroll
    for (int d = 0; d < 32; d++) acc[d] = 0.f;
    #pragma unroll
    for (int j = 0; j < 32; j++) {
        const float4* vr = (const float4*)Vs[j];
        float pj = s[j];
        #pragma unroll
        for (int d4 = 0; d4 < 8; d4++) {
            float4 vv = vr[d4];
            acc[d4 * 4 + 0] += pj * vv.x; acc[d4 * 4 + 1] += pj * vv.y;
            acc[d4 * 4 + 2] += pj * vv.z; acc[d4 * 4 + 3] += pj * vv.w;
        }
    }
    float inv = 1.f / lsum;
    float4* o4 = (float4*)(O + (size_t)tid * 131072 + base);
    #pragma unroll
    for (int d4 = 0; d4 < 8; d4++) {
        float4 oo;
        oo.x = acc[d4 * 4 + 0] * inv; oo.y = acc[d4 * 4 + 1] * inv;
        oo.z = acc[d4 * 4 + 2] * inv; oo.w = acc[d4 * 4 + 3] * inv;
        o4[d4] = oo;
    }
}

// ---------------------------------------------------------------------------
// Re-index long -> short, add pos (float4 vectorized)
// grid (16384) block (64)
// ---------------------------------------------------------------------------
__global__ void reindex_short() {
    int token2 = blockIdx.x;
    int s = token2 >> 5, b2 = token2 & 31;
    int t = s >> 8, rem = s & 255, ih = rem >> 4, iw = rem & 15;
    int nn = b2 >> 4, rr = b2 & 15, bh = rr >> 2, bw = rr & 3;
    int token = (t * 16 + bh * 4 + bw) * 512 + nn * 256 + ih * 16 + iw;
    int c4 = threadIdx.x;
    size_t si = (size_t)token * 64 + c4;
    size_t di = (size_t)token2 * 64 + c4;
    float4 x  = ((const float4*)g_mb)[si];
    float4 pp = ((const float4*)g_p)[si];
    float4 xp = make_float4(x.x + pp.x, x.y + pp.y, x.z + pp.z, x.w + pp.w);
    ((float4*)g_x0)[di] = xp;
    ((float4*)g_x2)[di] = x;
}

// ---------------------------------------------------------------------------
// Attention #2 (short): FA2 on mma.sync, truncation-split bf16, double-
// buffered K/V with one barrier per tile (proven).
// grid (4, 8, 32) block (256)
// ---------------------------------------------------------------------------
__global__ __launch_bounds__(256) void attn2_tc(const float* __restrict__ Q,
                                                const float* __restrict__ K,
                                                const float* __restrict__ V,
                                                float* __restrict__ O) {
    int qt = blockIdx.x, h = blockIdx.y, b2 = blockIdx.z;
    size_t base = (size_t)b2 * CDIM + h * DHEAD;
    __shared__ __nv_bfloat16 Kh[2][64 * LDSR], Kl[2][64 * LDSR];
    __shared__ __nv_bfloat16 Vh[2][64 * LDSR], Vl[2][64 * LDSR];

    int tid = threadIdx.x, warp = tid >> 5, lane = tid & 31;
    int al16 = lane & 15;
    int r  = lane >> 2;
    int cq = (lane & 3) * 2;
    int l0 = qt * 128 + warp * 16;

    uint32_t qh[2][4], ql[2][4];
    #pragma unroll
    for (int kf = 0; kf < 2; kf++) {
        #pragma unroll
        for (int half = 0; half < 2; half++) {
            int col = kf * 16 + half * 8 + cq;
            float2 v0 = *(const float2*)&Q[(size_t)(l0 + r) * 8192 + base + col];
            float2 v1 = *(const float2*)&Q[(size_t)(l0 + r + 8) * 8192 + base + col];
            v0.x *= SCALE; v0.y *= SCALE; v1.x *= SCALE; v1.y *= SCALE;
            pack_split(v0.x, v0.y, &qh[kf][half * 2 + 0], &ql[kf][half * 2 + 0]);
            pack_split(v1.x, v1.y, &qh[kf][half * 2 + 1], &ql[kf][half * 2 + 1]);
        }
    }

    float o[4][4];
    #pragma unroll
    for (int nf = 0; nf < 4; nf++)
        #pragma unroll
        for (int e = 0; e < 4; e++) o[nf][e] = 0.f;
    float mrow0 = -1e30f, mrow1 = -1e30f, lrow0 = 0.f, lrow1 = 0.f;

    const float4* K4 = (const float4*)K;
    const float4* V4 = (const float4*)V;
    int srow = tid >> 2;
    int sc4  = tid & 3;

    for (int kt = 0; kt < 8; kt++) {
        int buf = kt & 1;
        #pragma unroll
        for (int i = 0; i < 2; i++) {
            int c4 = sc4 + i * 4;
            size_t gidx = ((size_t)(kt * 64 + srow) * 8192 + base) / 4 + c4;
            float4 kv = K4[gidx];
            float4 vv = V4[gidx];
            split_store4(&Kh[buf][srow * LDSR + c4 * 4], &Kl[buf][srow * LDSR + c4 * 4], kv);
            split_store4(&Vh[buf][srow * LDSR + c4 * 4], &Vl[buf][srow * LDSR + c4 * 4], vv);
        }
        __syncthreads();

        float s[8][4];
        #pragma unroll
        for (int nf = 0; nf < 8; nf++) {
            s[nf][0] = s[nf][1] = s[nf][2] = s[nf][3] = 0.f;
        }
        #pragma unroll
        for (int kf = 0; kf < 2; kf++) {
            uint32_t bh[8][2], bl[8][2];
            #pragma unroll
            for (int nf = 0; nf < 8; nf++) {
                const __nv_bfloat16* pk = &Kh[buf][(nf * 8 + (al16 & 7)) * LDSR + (al16 >> 3) * 8 + kf * 16];
                const __nv_bfloat16* pl = &Kl[buf][(nf * 8 + (al16 & 7)) * LDSR + (al16 >> 3) * 8 + kf * 16];
                ldsm_x2(bh[nf], pk);
                ldsm_x2(bl[nf], pl);
            }
            #pragma unroll
            for (int nf = 0; nf < 8; nf++)
                mma_bf16(s[nf], qh[kf], bh[nf]);
            #pragma unroll
            for (int nf = 0; nf < 8; nf++)
                mma_bf16(s[nf], qh[kf], bl[nf]);
            #pragma unroll
            for (int nf = 0; nf < 8; nf++)
                mma_bf16(s[nf], ql[kf], bh[nf]);
        }

        float t0 = -1e30f, t1 = -1e30f;
        #pragma unroll
        for (int nf = 0; nf < 8; nf++) {
            t0 = fmaxf(t0, fmaxf(s[nf][0], s[nf][1]));
            t1 = fmaxf(t1, fmaxf(s[nf][2], s[nf][3]));
        }
        t0 = fmaxf(t0, __shfl_xor_sync(0xffffffffu, t0, 1));
        t0 = fmaxf(t0, __shfl_xor_sync(0xffffffffu, t0, 2));
        t1 = fmaxf(t1, __shfl_xor_sync(0xffffffffu, t1, 1));
        t1 = fmaxf(t1, __shfl_xor_sync(0xffffffffu, t1, 2));
        float mn0 = fmaxf(mrow0, t0), mn1 = fmaxf(mrow1, t1);
        float corr0 = __expf(mrow0 - mn0), corr1 = __expf(mrow1 - mn1);

        float rs0 = 0.f, rs1 = 0.f;
        #pragma unroll
        for (int nf = 0; nf < 8; nf++) {
            s[nf][0] = __expf(s[nf][0] - mn0); rs0 += s[nf][0];
            s[nf][1] = __expf(s[nf][1] - mn0); rs0 += s[nf][1];
            s[nf][2] = __expf(s[nf][2] - mn1); rs1 += s[nf][2];
            s[nf][3] = __expf(s[nf][3] - mn1); rs1 += s[nf][3];
        }
        rs0 += __shfl_xor_sync(0xffffffffu, rs0, 1);
        rs0 += __shfl_xor_sync(0xffffffffu, rs0, 2);
        rs1 += __shfl_xor_sync(0xffffffffu, rs1, 1);
        rs1 += __shfl_xor_sync(0xffffffffu, rs1, 2);
        lrow0 = lrow0 * corr0 + rs0;
        lrow1 = lrow1 * corr1 + rs1;
        mrow0 = mn0; mrow1 = mn1;

        #pragma unroll
        for (int nf = 0; nf < 4; nf++) {
            o[nf][0] *= corr0; o[nf][1] *= corr0;
            o[nf][2] *= corr1; o[nf][3] *= corr1;
        }

        #pragma unroll
        for (int kg = 0; kg < 4; kg++) {
            uint32_t ph[4], pl2[4];
            pack_split(s[2 * kg][0],     s[2 * kg][1],     &ph[0], &pl2[0]);
            pack_split(s[2 * kg][2],     s[2 * kg][3],     &ph[1], &pl2[1]);
            pack_split(s[2 * kg + 1][0], s[2 * kg + 1][1], &ph[2], &pl2[2]);
            pack_split(s[2 * kg + 1][2], s[2 * kg + 1][3], &ph[3], &pl2[3]);
            uint32_t vbh[4][2], vbl[4][2];
            #pragma unroll
            for (int nf = 0; nf < 4; nf++) {
                ldsm_x2_trans(vbh[nf], &Vh[buf][(kg * 16 + al16) * LDSR + nf * 8]);
                ldsm_x2_trans(vbl[nf], &Vl[buf][(kg * 16 + al16) * LDSR + nf * 8]);
            }
            #pragma unroll
            for (int nf = 0; nf < 4; nf++)
                mma_bf16(o[nf], ph, vbh[nf]);
            #pragma unroll
            for (int nf = 0; nf < 4; nf++)
                mma_bf16(o[nf], ph, vbl[nf]);
            #pragma unroll
            for (int nf = 0; nf < 4; nf++)
                mma_bf16(o[nf], pl2, vbh[nf]);
        }
    }

    float inv0 = 1.f / lrow0, inv1 = 1.f / lrow1;
    #pragma unroll
    for (int nf = 0; nf < 4; nf++) {
        int col = nf * 8 + cq;
        float2 o0 = make_float2(o[nf][0] * inv0, o[nf][1] * inv0);
        float2 o1 = make_float2(o[nf][2] * inv1, o[nf][3] * inv1);
        *(float2*)&O[(size_t)(l0 + r) * 8192 + base + col]     = o0;
        *(float2*)&O[(size_t)(l0 + r + 8) * 8192 + base + col] = o1;
    }
}

// ---------------------------------------------------------------------------
// Scatter: short token layout -> output [n,c,t,h,w]
// grid (16, 64, 4) block (32, 8)
// ---------------------------------------------------------------------------
__global__ void scatter_out(const float* __restrict__ src, float* __restrict__ out) {
    int ct = blockIdx.x >> 1, xt = blockIdx.x & 1;
    int y  = blockIdx.y;
    int nn = blockIdx.z >> 1, t = blockIdx.z & 1;
    int c0 = ct * 32, x0 = xt * 32;
    int bh = y >> 4, ih = y & 15;
    __shared__ float sm[32][33];
    int tx = threadIdx.x, ty = threadIdx.y;
    #pragma unroll
    for (int i = 0; i < 4; i++) {
        int xi = ty + i * 8;
        int x = x0 + xi;
        int bw = x >> 4, iw = x & 15;
        int s  = t * 256 + ih * 16 + iw;
        int b2 = nn * 16 + bh * 4 + bw;
        int token2 = s * 32 + b2;
        sm[tx][xi] = src[(size_t)token2 * CDIM + c0 + tx];
    }
    __syncthreads();
    #pragma unroll
    for (int i = 0; i < 4; i++) {
        int ci = ty + i * 8;
        out[((size_t)(nn * CDIM + c0 + ci) * 2 + t) * 4096 + (size_t)y * 64 + x0 + tx] = sm[ci][tx];
    }
}

// ---------------------------------------------------------------------------
extern "C" void kernel_launch(void* const* d_in, const int* in_sizes, int n_in,
                              void* d_out, int out_size) {
    (void)in_sizes; (void)n_in; (void)out_size;
    const float* q      = (const float*)d_in[0];
    const float* k      = (const float*)d_in[1];
    const float* v      = (const float*)d_in[2];
    const float* pos    = (const float*)d_in[3];
    const float* wl_in  = (const float*)d_in[4];
    const float* bl_in  = (const float*)d_in[5];
    const float* wl_out = (const float*)d_in[6];
    const float* bl_out = (const float*)d_in[7];
    const float* ws_in  = (const float*)d_in[8];
    const float* bs_in  = (const float*)d_in[9];
    const float* ws_out = (const float*)d_in[10];
    const float* bs_out = (const float*)d_in[11];
    float* out = (float*)d_out;

    float *px0, *px1, *px2, *pq, *pk, *pv, *po, *pm;
    cudaGetSymbolAddress((void**)&px0, g_x0);
    cudaGetSymbolAddress((void**)&px1, g_x1);
    cudaGetSymbolAddress((void**)&px2, g_x2);
    cudaGetSymbolAddress((void**)&pq,  g_qb);
    cudaGetSymbolAddress((void**)&pk,  g_kb);
    cudaGetSymbolAddress((void**)&pv,  g_vb);
    cudaGetSymbolAddress((void**)&po,  g_ob);
    cudaGetSymbolAddress((void**)&pm,  g_mb);

    dim3 gGather(16, 64, 4), bGather(32, 8);
    dim3 gGemm3(4, 128, 3);
    dim3 gGemm1(4, 128, 1);
    dim3 gAttn1(512, 8);
    dim3 gAttn2(4, 8, 32);

    // Phase 1: gather to long layout (+pos)
    gather_long<<<gGather, bGather>>>(q, k, v, pos);

    // Phase 2: MHA1 input projections — ONE fused launch (z selects Q/K/V)
    gemm_nt_tc<<<gGemm3, 256>>>(px0, px1, px2, wl_in, bl_in, pq, pk, pv);

    // Phase 3: long attention
    attn1<<<gAttn1, 32>>>(pq, pk, pv, po);

    // Phase 4: MHA1 output projection
    gemm_nt_tc<<<gGemm1, 256>>>(po, po, po, wl_out, bl_out, pm, pm, pm);

    // Phase 5: permute long -> short, add pos
    reindex_short<<<TOK, 64>>>();

    // Phase 6: MHA2 input projections — ONE fused launch (Q,K share x0)
    gemm_nt_tc<<<gGemm3, 256>>>(px0, px0, px2, ws_in, bs_in, pq, pk, pv);

    // Phase 7: short attention (tensor-core flash, double-buffered)
    attn2_tc<<<gAttn2, 256>>>(pq, pk, pv, po);

    // Phase 8: MHA2 output projection + scatter to output layout
    gemm_nt_tc<<<gGemm1, 256>>>(po, po, po, ws_out, bs_out, pm, pm, pm);
    scatter_out<<<gGather, bGather>>>(pm, out);
}

// round 17
// speedup vs baseline: 1.1026x; 1.0054x over previous
#include <cuda_runtime.h>
#include <cuda_bf16.h>
#include <cstdint>

// Problem constants
#define TOK   16384
#define CDIM  256
#define NHEAD 8
#define DHEAD 32
#define SCALE 0.17677669529663687f  // 1/sqrt(32)

// Scratch (static device globals — allocation-free per harness rules)
__device__ float g_x0[TOK * CDIM];
__device__ float g_x1[TOK * CDIM];
__device__ float g_x2[TOK * CDIM];
__device__ float g_p [TOK * CDIM];
__device__ float g_qb[TOK * CDIM];
__device__ float g_kb[TOK * CDIM];
__device__ float g_vb[TOK * CDIM];
__device__ float g_ob[TOK * CDIM];
__device__ float g_mb[TOK * CDIM];

// ---------------------------------------------------------------------------
// Common MMA helpers
// ---------------------------------------------------------------------------
#define LDSR 40   // padded smem row stride in bf16 (80B: ldmatrix conflict-free)

__device__ __forceinline__ void mma_bf16(float* d, const uint32_t* a, const uint32_t* b) {
    asm volatile(
        "mma.sync.aligned.m16n8k16.row.col.f32.bf16.bf16.f32 "
        "{%0,%1,%2,%3}, {%4,%5,%6,%7}, {%8,%9}, {%0,%1,%2,%3};"
        : "+f"(d[0]), "+f"(d[1]), "+f"(d[2]), "+f"(d[3])
        : "r"(a[0]), "r"(a[1]), "r"(a[2]), "r"(a[3]), "r"(b[0]), "r"(b[1]));
}

__device__ __forceinline__ void ldsm_x4(uint32_t* r, const __nv_bfloat16* p) {
    uint32_t addr = (uint32_t)__cvta_generic_to_shared(p);
    asm volatile("ldmatrix.sync.aligned.m8n8.x4.shared.b16 {%0,%1,%2,%3}, [%4];"
                 : "=r"(r[0]), "=r"(r[1]), "=r"(r[2]), "=r"(r[3]) : "r"(addr));
}

__device__ __forceinline__ void ldsm_x2(uint32_t* r, const __nv_bfloat16* p) {
    uint32_t addr = (uint32_t)__cvta_generic_to_shared(p);
    asm volatile("ldmatrix.sync.aligned.m8n8.x2.shared.b16 {%0,%1}, [%2];"
                 : "=r"(r[0]), "=r"(r[1]) : "r"(addr));
}

__device__ __forceinline__ void ldsm_x2_trans(uint32_t* r, const __nv_bfloat16* p) {
    uint32_t addr = (uint32_t)__cvta_generic_to_shared(p);
    asm volatile("ldmatrix.sync.aligned.m8n8.x2.trans.shared.b16 {%0,%1}, [%2];"
                 : "=r"(r[0]), "=r"(r[1]) : "r"(addr));
}

// Truncation split: hi = top-16 bits of fp32 (packed via PRMT), lo = rn(x - hi).
__device__ __forceinline__ void pack_split(float x, float y, uint32_t* hi, uint32_t* lo) {
    uint32_t ux = __float_as_uint(x), uy = __float_as_uint(y);
    *hi = __byte_perm(ux, uy, 0x7632);
    float lx = x - __uint_as_float(ux & 0xFFFF0000u);
    float ly = y - __uint_as_float(uy & 0xFFFF0000u);
    __nv_bfloat162 lp = __floats2bfloat162_rn(lx, ly);
    *lo = *(uint32_t*)&lp;
}

// float4 (4 consecutive k) -> 2 packed hi words + 2 packed lo words, STS.64.
__device__ __forceinline__ void split_store4(__nv_bfloat16* hp, __nv_bfloat16* lp, float4 v) {
    uint32_t h01, h23, l01, l23;
    pack_split(v.x, v.y, &h01, &l01);
    pack_split(v.z, v.w, &h23, &l23);
    uint2 hw; hw.x = h01; hw.y = h23;
    uint2 lw; lw.x = l01; lw.y = l23;
    *(uint2*)hp = hw;
    *(uint2*)lp = lw;
}

// ---------------------------------------------------------------------------
// Gather: [n,c,t,h,w] -> long token layout [token= l*512+b, c]
// ---------------------------------------------------------------------------
__global__ void gather_long(const float* __restrict__ q, const float* __restrict__ k,
                            const float* __restrict__ v, const float* __restrict__ p) {
    int ct = blockIdx.x >> 1, xt = blockIdx.x & 1;
    int y  = blockIdx.y;
    int nn = blockIdx.z >> 1, t = blockIdx.z & 1;
    int c0 = ct * 32, x0 = xt * 32;
    __shared__ float sq[32][33], sk[32][33], sv[32][33], sp[32][33];
    int tx = threadIdx.x, ty = threadIdx.y;
    #pragma unroll
    for (int i = 0; i < 4; i++) {
        int ci = ty + i * 8;
        size_t idx = ((size_t)(nn * CDIM + c0 + ci) * 2 + t) * 4096 + (size_t)y * 64 + x0 + tx;
        float pv = p[idx];
        sq[ci][tx] = q[idx] + pv;
        sk[ci][tx] = k[idx] + pv;
        sv[ci][tx] = v[idx];
        sp[ci][tx] = pv;
    }
    __syncthreads();
    int bh = y >> 4, ih = y & 15;
    #pragma unroll
    for (int i = 0; i < 4; i++) {
        int xi = ty + i * 8;
        int x = x0 + xi;
        int bw = x >> 4, iw = x & 15;
        int token = (t * 16 + bh * 4 + bw) * 512 + nn * 256 + ih * 16 + iw;
        size_t o = (size_t)token * CDIM + c0 + tx;
        g_x0[o] = sq[tx][xi];
        g_x1[o] = sk[tx][xi];
        g_x2[o] = sv[tx][xi];
        g_p [o] = sp[tx][xi];
    }
}

// ---------------------------------------------------------------------------
// Tensor-core GEMM: BM=64 BN=64 BK=32, 128 threads = 4 warps (2m x 2n);
// warp-level code identical to the proven kernel (32x32 warp tile, STS.64
// lcol4 staging map, B frags via ldsm_x4, truncation-split bf16, double-
// buffered smem with one sync per kt). 4 CTAs/SM -> 4-warp barrier convoys
// with 3 co-resident CTAs covering each stall.
// grid (4, 256, nz)  block (128)
// ---------------------------------------------------------------------------
__global__ __launch_bounds__(128, 4) void gemm_nt_tc(const float* __restrict__ X0,
                                                     const float* __restrict__ X1,
                                                     const float* __restrict__ X2,
                                                     const float* __restrict__ W0,
                                                     const float* __restrict__ bias0,
                                                     float* __restrict__ Y0,
                                                     float* __restrict__ Y1,
                                                     float* __restrict__ Y2) {
    __shared__ __nv_bfloat16 As_hi[2][64 * LDSR], As_lo[2][64 * LDSR];
    __shared__ __nv_bfloat16 Bs_hi[2][64 * LDSR], Bs_lo[2][64 * LDSR];

    int bz = blockIdx.z;
    const float* X = (bz == 0) ? X0 : ((bz == 1) ? X1 : X2);
    float*       Y = (bz == 0) ? Y0 : ((bz == 1) ? Y1 : Y2);
    const float* Wm   = W0 + (size_t)bz * 65536;
    const float* bias = bias0 + bz * 256;

    int tid  = threadIdx.x;
    int warp = tid >> 5, lane = tid & 31;
    int m0 = blockIdx.y * 64, n0 = blockIdx.x * 64;
    int wm = (warp >> 1) * 32;
    int wn = (warp & 1) * 32;

    float acc[2][4][4];
    #pragma unroll
    for (int mi = 0; mi < 2; mi++)
        #pragma unroll
        for (int ni = 0; ni < 4; ni++)
            #pragma unroll
            for (int e = 0; e < 4; e++) acc[mi][ni][e] = 0.f;

    const float4* X4 = (const float4*)X;
    const float4* W4 = (const float4*)Wm;
    int lrow  = tid >> 3;   // 0..15
    int lcol4 = tid & 7;

    int al16 = lane & 15;
    int offA = (wm + al16) * LDSR + (lane >> 4) * 8;
    int offB = (wn + al16) * LDSR + (lane >> 4) * 8;

    float4 xa[4], wb[4];
    #pragma unroll
    for (int i = 0; i < 4; i++) {
        xa[i] = X4[(size_t)(m0 + lrow + i * 16) * 64 + lcol4];
        wb[i] = W4[(size_t)(n0 + lrow + i * 16) * 64 + lcol4];
    }

    for (int kt = 0; kt < 8; kt++) {
        int buf = kt & 1;
        #pragma unroll
        for (int i = 0; i < 4; i++) {
            int r = lrow + i * 16;
            split_store4(&As_hi[buf][r * LDSR + lcol4 * 4],
                         &As_lo[buf][r * LDSR + lcol4 * 4], xa[i]);
            split_store4(&Bs_hi[buf][r * LDSR + lcol4 * 4],
                         &Bs_lo[buf][r * LDSR + lcol4 * 4], wb[i]);
        }
        __syncthreads();

        if (kt < 7) {
            #pragma unroll
            for (int i = 0; i < 4; i++) {
                xa[i] = X4[(size_t)(m0 + lrow + i * 16) * 64 + (kt + 1) * 8 + lcol4];
                wb[i] = W4[(size_t)(n0 + lrow + i * 16) * 64 + (kt + 1) * 8 + lcol4];
            }
        }

        const __nv_bfloat16* pa_hi0 = &As_hi[buf][offA];
        const __nv_bfloat16* pa_lo0 = &As_lo[buf][offA];
        const __nv_bfloat16* pb_hi0 = &Bs_hi[buf][offB];
        const __nv_bfloat16* pb_lo0 = &Bs_lo[buf][offB];

        #pragma unroll
        for (int kk = 0; kk < 2; kk++) {
            int ko = kk * 16;
            uint32_t ah[2][4], al[2][4];
            #pragma unroll
            for (int mi = 0; mi < 2; mi++) {
                ldsm_x4(ah[mi], pa_hi0 + mi * 16 * LDSR + ko);
                ldsm_x4(al[mi], pa_lo0 + mi * 16 * LDSR + ko);
            }
            uint32_t bh[4][2], bl[4][2];
            #pragma unroll
            for (int ni2 = 0; ni2 < 2; ni2++) {
                uint32_t r4[4];
                ldsm_x4(r4, pb_hi0 + ni2 * 16 * LDSR + ko);
                bh[2 * ni2][0] = r4[0]; bh[2 * ni2][1] = r4[2];
                bh[2 * ni2 + 1][0] = r4[1]; bh[2 * ni2 + 1][1] = r4[3];
                ldsm_x4(r4, pb_lo0 + ni2 * 16 * LDSR + ko);
                bl[2 * ni2][0] = r4[0]; bl[2 * ni2][1] = r4[2];
                bl[2 * ni2 + 1][0] = r4[1]; bl[2 * ni2 + 1][1] = r4[3];
            }
            #pragma unroll
            for (int mi = 0; mi < 2; mi++)
                #pragma unroll
                for (int ni = 0; ni < 4; ni++) {
                    mma_bf16(acc[mi][ni], ah[mi], bh[ni]);
                    mma_bf16(acc[mi][ni], ah[mi], bl[ni]);
                    mma_bf16(acc[mi][ni], al[mi], bh[ni]);
                }
        }
    }

    int cr = lane >> 2;
    int cc = (lane & 3) * 2;
    #pragma unroll
    for (int mi = 0; mi < 2; mi++) {
        #pragma unroll
        for (int ni = 0; ni < 4; ni++) {
            int col = n0 + wn + ni * 8 + cc;
            float b0 = bias[col], b1 = bias[col + 1];
            int row0 = m0 + wm + mi * 16 + cr;
            float2 o0 = make_float2(acc[mi][ni][0] + b0, acc[mi][ni][1] + b1);
            float2 o1 = make_float2(acc[mi][ni][2] + b0, acc[mi][ni][3] + b1);
            *(float2*)&Y[(size_t)row0 * CDIM + col]       = o0;
            *(float2*)&Y[(size_t)(row0 + 8) * CDIM + col] = o1;
        }
    }
}

// ---------------------------------------------------------------------------
// Attention #1 (long): Lq=Lk=32, d=32; one warp per (b,h); thread = query row.
// grid (512, 8) block (32)
// ---------------------------------------------------------------------------
__global__ void attn1(const float* __restrict__ Q, const float* __restrict__ K,
                      const float* __restrict__ V, float* __restrict__ O) {
    int b = blockIdx.x, h = blockIdx.y;
    size_t base = (size_t)b * CDIM + h * DHEAD;
    __shared__ float Ks[32][36], Vs[32][36];
    int tid = threadIdx.x;
    for (int r = 0; r < 32; r++) {
        size_t idx = (size_t)r * 131072 + base + tid;
        Ks[r][tid] = K[idx];
        Vs[r][tid] = V[idx];
    }
    __syncthreads();
    float q[32];
    const float4* q4 = (const float4*)(Q + (size_t)tid * 131072 + base);
    #pragma unroll
    for (int d4 = 0; d4 < 8; d4++) {
        float4 qq = q4[d4];
        q[d4 * 4 + 0] = qq.x * SCALE; q[d4 * 4 + 1] = qq.y * SCALE;
        q[d4 * 4 + 2] = qq.z * SCALE; q[d4 * 4 + 3] = qq.w * SCALE;
    }
    float s[32];
    float m = -1e30f;
    #pragma unroll
    for (int j = 0; j < 32; j++) {
        const float4* kr = (const float4*)Ks[j];
        float a = 0.f;
        #pragma unroll
        for (int d4 = 0; d4 < 8; d4++) {
            float4 kv = kr[d4];
            a += q[d4 * 4 + 0] * kv.x + q[d4 * 4 + 1] * kv.y
               + q[d4 * 4 + 2] * kv.z + q[d4 * 4 + 3] * kv.w;
        }
        s[j] = a;
        m = fmaxf(m, a);
    }
    float lsum = 0.f;
    #pragma unroll
    for (int j = 0; j < 32; j++) { s[j] = __expf(s[j] - m); lsum += s[j]; }
    float acc[32];
    #pragma unroll
    for (int d = 0; d < 32; d++) acc[d] = 0.f;
    #pragma unroll
    for (int j = 0; j < 32; j++) {
        const float4* vr = (const float4*)Vs[j];
        float pj = s[j];
        #pragma unroll
        for (int d4 = 0; d4 < 8; d4++) {
            float4 vv = vr[d4];
            acc[d4 * 4 + 0] += pj * vv.x; acc[d4 * 4 + 1] += pj * vv.y;
            acc[d4 * 4 + 2] += pj * vv.z; acc[d4 * 4 + 3] += pj * vv.w;
        }
    }
    float inv = 1.f / lsum;
    float4* o4 = (float4*)(O + (size_t)tid * 131072 + base);
    #pragma unroll
    for (int d4 = 0; d4 < 8; d4++) {
        float4 oo;
        oo.x = acc[d4 * 4 + 0] * inv; oo.y = acc[d4 * 4 + 1] * inv;
        oo.z = acc[d4 * 4 + 2] * inv; oo.w = acc[d4 * 4 + 3] * inv;
        o4[d4] = oo;
    }
}

// ---------------------------------------------------------------------------
// Re-index long -> short, add pos (float4 vectorized)
// grid (16384) block (64)
// ---------------------------------------------------------------------------
__global__ void reindex_short() {
    int token2 = blockIdx.x;
    int s = token2 >> 5, b2 = token2 & 31;
    int t = s >> 8, rem = s & 255, ih = rem >> 4, iw = rem & 15;
    int nn = b2 >> 4, rr = b2 & 15, bh = rr >> 2, bw = rr & 3;
    int token = (t * 16 + bh * 4 + bw) * 512 + nn * 256 + ih * 16 + iw;
    int c4 = threadIdx.x;
    size_t si = (size_t)token * 64 + c4;
    size_t di = (size_t)token2 * 64 + c4;
    float4 x  = ((const float4*)g_mb)[si];
    float4 pp = ((const float4*)g_p)[si];
    float4 xp = make_float4(x.x + pp.x, x.y + pp.y, x.z + pp.z, x.w + pp.w);
    ((float4*)g_x0)[di] = xp;
    ((float4*)g_x2)[di] = x;
}

// ---------------------------------------------------------------------------
// Attention #2 (short): FA2 on mma.sync, truncation-split bf16, double-
// buffered K/V with one barrier per tile (proven).
// grid (4, 8, 32) block (256)
// ---------------------------------------------------------------------------
__global__ __launch_bounds__(256) void attn2_tc(const float* __restrict__ Q,
                                                const float* __restrict__ K,
                                                const float* __restrict__ V,
                                                float* __restrict__ O) {
    int qt = blockIdx.x, h = blockIdx.y, b2 = blockIdx.z;
    size_t base = (size_t)b2 * CDIM + h * DHEAD;
    __shared__ __nv_bfloat16 Kh[2][64 * LDSR], Kl[2][64 * LDSR];
    __shared__ __nv_bfloat16 Vh[2][64 * LDSR], Vl[2][64 * LDSR];

    int tid = threadIdx.x, warp = tid >> 5, lane = tid & 31;
    int al16 = lane & 15;
    int r  = lane >> 2;
    int cq = (lane & 3) * 2;
    int l0 = qt * 128 + warp * 16;

    uint32_t qh[2][4], ql[2][4];
    #pragma unroll
    for (int kf = 0; kf < 2; kf++) {
        #pragma unroll
        for (int half = 0; half < 2; half++) {
            int col = kf * 16 + half * 8 + cq;
            float2 v0 = *(const float2*)&Q[(size_t)(l0 + r) * 8192 + base + col];
            float2 v1 = *(const float2*)&Q[(size_t)(l0 + r + 8) * 8192 + base + col];
            v0.x *= SCALE; v0.y *= SCALE; v1.x *= SCALE; v1.y *= SCALE;
            pack_split(v0.x, v0.y, &qh[kf][half * 2 + 0], &ql[kf][half * 2 + 0]);
            pack_split(v1.x, v1.y, &qh[kf][half * 2 + 1], &ql[kf][half * 2 + 1]);
        }
    }

    float o[4][4];
    #pragma unroll
    for (int nf = 0; nf < 4; nf++)
        #pragma unroll
        for (int e = 0; e < 4; e++) o[nf][e] = 0.f;
    float mrow0 = -1e30f, mrow1 = -1e30f, lrow0 = 0.f, lrow1 = 0.f;

    const float4* K4 = (const float4*)K;
    const float4* V4 = (const float4*)V;
    int srow = tid >> 2;
    int sc4  = tid & 3;

    for (int kt = 0; kt < 8; kt++) {
        int buf = kt & 1;
        #pragma unroll
        for (int i = 0; i < 2; i++) {
            int c4 = sc4 + i * 4;
            size_t gidx = ((size_t)(kt * 64 + srow) * 8192 + base) / 4 + c4;
            float4 kv = K4[gidx];
            float4 vv = V4[gidx];
            split_store4(&Kh[buf][srow * LDSR + c4 * 4], &Kl[buf][srow * LDSR + c4 * 4], kv);
            split_store4(&Vh[buf][srow * LDSR + c4 * 4], &Vl[buf][srow * LDSR + c4 * 4], vv);
        }
        __syncthreads();

        float s[8][4];
        #pragma unroll
        for (int nf = 0; nf < 8; nf++) {
            s[nf][0] = s[nf][1] = s[nf][2] = s[nf][3] = 0.f;
        }
        #pragma unroll
        for (int kf = 0; kf < 2; kf++) {
            uint32_t bh[8][2], bl[8][2];
            #pragma unroll
            for (int nf = 0; nf < 8; nf++) {
                const __nv_bfloat16* pk = &Kh[buf][(nf * 8 + (al16 & 7)) * LDSR + (al16 >> 3) * 8 + kf * 16];
                const __nv_bfloat16* pl = &Kl[buf][(nf * 8 + (al16 & 7)) * LDSR + (al16 >> 3) * 8 + kf * 16];
                ldsm_x2(bh[nf], pk);
                ldsm_x2(bl[nf], pl);
            }
            #pragma unroll
            for (int nf = 0; nf < 8; nf++)
                mma_bf16(s[nf], qh[kf], bh[nf]);
            #pragma unroll
            for (int nf = 0; nf < 8; nf++)
                mma_bf16(s[nf], qh[kf], bl[nf]);
            #pragma unroll
            for (int nf = 0; nf < 8; nf++)
                mma_bf16(s[nf], ql[kf], bh[nf]);
        }

        float t0 = -1e30f, t1 = -1e30f;
        #pragma unroll
        for (int nf = 0; nf < 8; nf++) {
            t0 = fmaxf(t0, fmaxf(s[nf][0], s[nf][1]));
            t1 = fmaxf(t1, fmaxf(s[nf][2], s[nf][3]));
        }
        t0 = fmaxf(t0, __shfl_xor_sync(0xffffffffu, t0, 1));
        t0 = fmaxf(t0, __shfl_xor_sync(0xffffffffu, t0, 2));
        t1 = fmaxf(t1, __shfl_xor_sync(0xffffffffu, t1, 1));
        t1 = fmaxf(t1, __shfl_xor_sync(0xffffffffu, t1, 2));
        float mn0 = fmaxf(mrow0, t0), mn1 = fmaxf(mrow1, t1);
        float corr0 = __expf(mrow0 - mn0), corr1 = __expf(mrow1 - mn1);

        float rs0 = 0.f, rs1 = 0.f;
        #pragma unroll
        for (int nf = 0; nf < 8; nf++) {
            s[nf][0] = __expf(s[nf][0] - mn0); rs0 += s[nf][0];
            s[nf][1] = __expf(s[nf][1] - mn0); rs0 += s[nf][1];
            s[nf][2] = __expf(s[nf][2] - mn1); rs1 += s[nf][2];
            s[nf][3] = __expf(s[nf][3] - mn1); rs1 += s[nf][3];
        }
        rs0 += __shfl_xor_sync(0xffffffffu, rs0, 1);
        rs0 += __shfl_xor_sync(0xffffffffu, rs0, 2);
        rs1 += __shfl_xor_sync(0xffffffffu, rs1, 1);
        rs1 += __shfl_xor_sync(0xffffffffu, rs1, 2);
        lrow0 = lrow0 * corr0 + rs0;
        lrow1 = lrow1 * corr1 + rs1;
        mrow0 = mn0; mrow1 = mn1;

        #pragma unroll
        for (int nf = 0; nf < 4; nf++) {
            o[nf][0] *= corr0; o[nf][1] *= corr0;
            o[nf][2] *= corr1; o[nf][3] *= corr1;
        }

        #pragma unroll
        for (int kg = 0; kg < 4; kg++) {
            uint32_t ph[4], pl2[4];
            pack_split(s[2 * kg][0],     s[2 * kg][1],     &ph[0], &pl2[0]);
            pack_split(s[2 * kg][2],     s[2 * kg][3],     &ph[1], &pl2[1]);
            pack_split(s[2 * kg + 1][0], s[2 * kg + 1][1], &ph[2], &pl2[2]);
            pack_split(s[2 * kg + 1][2], s[2 * kg + 1][3], &ph[3], &pl2[3]);
            uint32_t vbh[4][2], vbl[4][2];
            #pragma unroll
            for (int nf = 0; nf < 4; nf++) {
                ldsm_x2_trans(vbh[nf], &Vh[buf][(kg * 16 + al16) * LDSR + nf * 8]);
                ldsm_x2_trans(vbl[nf], &Vl[buf][(kg * 16 + al16) * LDSR + nf * 8]);
            }
            #pragma unroll
            for (int nf = 0; nf < 4; nf++)
                mma_bf16(o[nf], ph, vbh[nf]);
            #pragma unroll
            for (int nf = 0; nf < 4; nf++)
                mma_bf16(o[nf], ph, vbl[nf]);
            #pragma unroll
            for (int nf = 0; nf < 4; nf++)
                mma_bf16(o[nf], pl2, vbh[nf]);
        }
    }

    float inv0 = 1.f / lrow0, inv1 = 1.f / lrow1;
    #pragma unroll
    for (int nf = 0; nf < 4; nf++) {
        int col = nf * 8 + cq;
        float2 o0 = make_float2(o[nf][0] * inv0, o[nf][1] * inv0);
        float2 o1 = make_float2(o[nf][2] * inv1, o[nf][3] * inv1);
        *(float2*)&O[(size_t)(l0 + r) * 8192 + base + col]     = o0;
        *(float2*)&O[(size_t)(l0 + r + 8) * 8192 + base + col] = o1;
    }
}

// ---------------------------------------------------------------------------
// Scatter: short token layout -> output [n,c,t,h,w]
// grid (16, 64, 4) block (32, 8)
// ---------------------------------------------------------------------------
__global__ void scatter_out(const float* __restrict__ src, float* __restrict__ out) {
    int ct = blockIdx.x >> 1, xt = blockIdx.x & 1;
    int y  = blockIdx.y;
    int nn = blockIdx.z >> 1, t = blockIdx.z & 1;
    int c0 = ct * 32, x0 = xt * 32;
    int bh = y >> 4, ih = y & 15;
    __shared__ float sm[32][33];
    int tx = threadIdx.x, ty = threadIdx.y;
    #pragma unroll
    for (int i = 0; i < 4; i++) {
        int xi = ty + i * 8;
        int x = x0 + xi;
        int bw = x >> 4, iw = x & 15;
        int s  = t * 256 + ih * 16 + iw;
        int b2 = nn * 16 + bh * 4 + bw;
        int token2 = s * 32 + b2;
        sm[tx][xi] = src[(size_t)token2 * CDIM + c0 + tx];
    }
    __syncthreads();
    #pragma unroll
    for (int i = 0; i < 4; i++) {
        int ci = ty + i * 8;
        out[((size_t)(nn * CDIM + c0 + ci) * 2 + t) * 4096 + (size_t)y * 64 + x0 + tx] = sm[ci][tx];
    }
}

// ---------------------------------------------------------------------------
extern "C" void kernel_launch(void* const* d_in, const int* in_sizes, int n_in,
                              void* d_out, int out_size) {
    (void)in_sizes; (void)n_in; (void)out_size;
    const float* q      = (const float*)d_in[0];
    const float* k      = (const float*)d_in[1];
    const float* v      = (const float*)d_in[2];
    const float* pos    = (const float*)d_in[3];
    const float* wl_in  = (const float*)d_in[4];
    const float* bl_in  = (const float*)d_in[5];
    const float* wl_out = (const float*)d_in[6];
    const float* bl_out = (const float*)d_in[7];
    const float* ws_in  = (const float*)d_in[8];
    const float* bs_in  = (const float*)d_in[9];
    const float* ws_out = (const float*)d_in[10];
    const float* bs_out = (const float*)d_in[11];
    float* out = (float*)d_out;

    float *px0, *px1, *px2, *pq, *pk, *pv, *po, *pm;
    cudaGetSymbolAddress((void**)&px0, g_x0);
    cudaGetSymbolAddress((void**)&px1, g_x1);
    cudaGetSymbolAddress((void**)&px2, g_x2);
    cudaGetSymbolAddress((void**)&pq,  g_qb);
    cudaGetSymbolAddress((void**)&pk,  g_kb);
    cudaGetSymbolAddress((void**)&pv,  g_vb);
    cudaGetSymbolAddress((void**)&po,  g_ob);
    cudaGetSymbolAddress((void**)&pm,  g_mb);

    dim3 gGather(16, 64, 4), bGather(32, 8);
    dim3 gGemm3(4, 256, 3);
    dim3 gGemm1(4, 256, 1);
    dim3 gAttn1(512, 8);
    dim3 gAttn2(4, 8, 32);

    // Phase 1: gather to long layout (+pos)
    gather_long<<<gGather, bGather>>>(q, k, v, pos);

    // Phase 2: MHA1 input projections — ONE fused launch (z selects Q/K/V)
    gemm_nt_tc<<<gGemm3, 128>>>(px0, px1, px2, wl_in, bl_in, pq, pk, pv);

    // Phase 3: long attention
    attn1<<<gAttn1, 32>>>(pq, pk, pv, po);

    // Phase 4: MHA1 output projection
    gemm_nt_tc<<<gGemm1, 128>>>(po, po, po, wl_out, bl_out, pm, pm, pm);

    // Phase 5: permute long -> short, add pos
    reindex_short<<<TOK, 64>>>();

    // Phase 6: MHA2 input projections — ONE fused launch (Q,K share x0)
    gemm_nt_tc<<<gGemm3, 128>>>(px0, px0, px2, ws_in, bs_in, pq, pk, pv);

    // Phase 7: short attention (tensor-core flash, double-buffered)
    attn2_tc<<<gAttn2, 256>>>(pq, pk, pv, po);

    // Phase 8: MHA2 output projection + scatter to output layout
    gemm_nt_tc<<<gGemm1, 128>>>(po, po, po, ws_out, bs_out, pm, pm, pm);
    scatter_out<<<gGather, bGather>>>(pm, out);
}